// round 8
// baseline (speedup 1.0000x reference)
#include <cuda_runtime.h>
#include <cuda_fp16.h>
#include <cstdint>

#define BB 2
#define SS 2048
#define DM 1024
#define NH 16
#define DK 64
#define NROWS (BB * SS)
#define OUT_ELEMS (NROWS * DM)
#define ATTN_ELEMS (2LL * 16 * 2048 * 2048)
#define INV_TEMP 0.35355339059327373f

typedef __half fp16;

// ------------------------- device scratch (no allocs) -----------------------
__device__ __align__(128) fp16  g_qn_hi[NROWS * DM], g_qn_lo[NROWS * DM];
__device__ __align__(128) fp16  g_ki_hi[NROWS * DM], g_ki_lo[NROWS * DM];
__device__ __align__(128) fp16  g_vi_hi[NROWS * DM], g_vi_lo[NROWS * DM];
__device__ __align__(128) fp16  g_wq_hi[DM * DM];
__device__ __align__(128) fp16  g_wk_hi[DM * DM];
__device__ __align__(128) fp16  g_wv_hi[DM * DM];
__device__ __align__(128) fp16  g_wf_hi[DM * DM];
__device__ __align__(128) fp16  g_qh_hi[NROWS * DM], g_qh_lo[NROWS * DM];
__device__ __align__(128) fp16  g_kh_hi[NROWS * DM], g_kh_lo[NROWS * DM];
__device__ __align__(128) fp16  g_vh_hi[NROWS * DM], g_vh_lo[NROWS * DM];
__device__ __align__(128) fp16  g_oh_hi[NROWS * DM], g_oh_lo[NROWS * DM];
__device__ __align__(128) float g_P[BB * NH * DK * DK];
__device__ int g_flag;

// ------------------------- helpers ------------------------------------------
__device__ __forceinline__ uint32_t smem_u32(const void* p) {
    uint32_t a;
    asm("{ .reg .u64 t; cvta.to.shared.u64 t, %1; cvt.u32.u64 %0, t; }"
        : "=r"(a) : "l"(p));
    return a;
}
__device__ __forceinline__ void cp16(uint32_t saddr, const void* g) {
    asm volatile("cp.async.cg.shared.global [%0], [%1], 16;"
                 :: "r"(saddr), "l"(g) : "memory");
}
__device__ __forceinline__ void cp_commit() {
    asm volatile("cp.async.commit_group;" ::: "memory");
}
__device__ __forceinline__ void cp_wait0() {
    asm volatile("cp.async.wait_group 0;" ::: "memory");
}
__device__ __forceinline__ void cp_wait1() {
    asm volatile("cp.async.wait_group 1;" ::: "memory");
}
__device__ __forceinline__ void ldsm4(uint32_t* r, uint32_t addr) {
    asm volatile("ldmatrix.sync.aligned.m8n8.x4.shared.b16 {%0,%1,%2,%3}, [%4];"
                 : "=r"(r[0]), "=r"(r[1]), "=r"(r[2]), "=r"(r[3]) : "r"(addr));
}
__device__ __forceinline__ void mma16816(float* d, const uint32_t* a,
                                         const uint32_t* b) {
    asm volatile(
        "mma.sync.aligned.m16n8k16.row.col.f32.f16.f16.f32 "
        "{%0,%1,%2,%3}, {%4,%5,%6,%7}, {%8,%9}, {%0,%1,%2,%3};"
        : "+f"(d[0]), "+f"(d[1]), "+f"(d[2]), "+f"(d[3])
        : "r"(a[0]), "r"(a[1]), "r"(a[2]), "r"(a[3]), "r"(b[0]), "r"(b[1]));
}
__device__ __forceinline__ void split_pair(float x, float y, __half2* hi,
                                           __half2* lo) {
    __half2 h = __floats2half2_rn(x, y);
    *hi = h;
    *lo = __floats2half2_rn(x - __half2float(__low2half(h)),
                            y - __half2float(__high2half(h)));
}

// ------------------------- small prep kernels --------------------------------
__global__ void initk() {
    int i = blockIdx.x * 256 + threadIdx.x;
    if (i < BB * NH * DK * DK) g_P[i] = 0.0f;
    if (i == 0) g_flag = 1;
}

// fallback full-mask check (only used when attn buffer absent)
__global__ void maskchk(const int* __restrict__ mask) {
    const int4* m4 = reinterpret_cast<const int4*>(mask);
    const size_t total = (size_t)BB * SS * SS / 4;
    size_t i = (size_t)blockIdx.x * 256 + threadIdx.x;
    size_t stride = (size_t)gridDim.x * 256;
    int bad = 0;
    for (size_t j = i; j < total; j += stride) {
        int4 m = __ldcs(&m4[j]);
        if (!(m.x && m.y && m.z && m.w)) bad = 1;
    }
    if (bad) g_flag = 0;
}

__global__ void ln_kernel(const float* __restrict__ q,
                          const float* __restrict__ gamma,
                          const float* __restrict__ beta,
                          fp16* __restrict__ out_hi, fp16* __restrict__ out_lo) {
    __shared__ float red[16];
    const int row = blockIdx.x;
    const int tid = threadIdx.x;
    const float4 v = reinterpret_cast<const float4*>(q)[row * 256 + tid];
    float s  = v.x + v.y + v.z + v.w;
    float s2 = v.x * v.x + v.y * v.y + v.z * v.z + v.w * v.w;
    #pragma unroll
    for (int o = 16; o > 0; o >>= 1) {
        s  += __shfl_xor_sync(0xffffffffu, s,  o);
        s2 += __shfl_xor_sync(0xffffffffu, s2, o);
    }
    if ((tid & 31) == 0) { red[tid >> 5] = s; red[8 + (tid >> 5)] = s2; }
    __syncthreads();
    if (tid < 32) {
        s  = (tid < 8) ? red[tid]     : 0.0f;
        s2 = (tid < 8) ? red[8 + tid] : 0.0f;
        #pragma unroll
        for (int o = 4; o > 0; o >>= 1) {
            s  += __shfl_xor_sync(0xffffffffu, s,  o);
            s2 += __shfl_xor_sync(0xffffffffu, s2, o);
        }
        if (tid == 0) { red[0] = s; red[8] = s2; }
    }
    __syncthreads();
    const float mu   = red[0] * (1.0f / 1024.0f);
    const float var  = red[8] * (1.0f / 1024.0f) - mu * mu;
    const float rstd = rsqrtf(var + 1e-6f);
    const float4 g  = reinterpret_cast<const float4*>(gamma)[tid];
    const float4 bb = reinterpret_cast<const float4*>(beta)[tid];
    float y0 = ((v.x - mu) * rstd * g.x + bb.x) * INV_TEMP;
    float y1 = ((v.y - mu) * rstd * g.y + bb.y) * INV_TEMP;
    float y2 = ((v.z - mu) * rstd * g.z + bb.z) * INV_TEMP;
    float y3 = ((v.w - mu) * rstd * g.w + bb.w) * INV_TEMP;
    __half2 h0, l0, h1, l1;
    split_pair(y0, y1, &h0, &l0);
    split_pair(y2, y3, &h1, &l1);
    __half2* oh = reinterpret_cast<__half2*>(out_hi);
    __half2* ol = reinterpret_cast<__half2*>(out_lo);
    const int b2 = (row * 256 + tid) * 2;
    oh[b2] = h0; oh[b2 + 1] = h1;
    ol[b2] = l0; ol[b2 + 1] = l1;
}

__global__ void splitk(const float* __restrict__ x, fp16* __restrict__ hi,
                       fp16* __restrict__ lo, int n4) {
    int i = blockIdx.x * 256 + threadIdx.x;
    if (i >= n4) return;
    float4 v = reinterpret_cast<const float4*>(x)[i];
    __half2 h0, l0, h1, l1;
    split_pair(v.x, v.y, &h0, &l0);
    split_pair(v.z, v.w, &h1, &l1);
    reinterpret_cast<__half2*>(hi)[i * 2]     = h0;
    reinterpret_cast<__half2*>(hi)[i * 2 + 1] = h1;
    reinterpret_cast<__half2*>(lo)[i * 2]     = l0;
    reinterpret_cast<__half2*>(lo)[i * 2 + 1] = l1;
}

// W[K][N] -> WT[n][k] hi fp16 (transpose)
__global__ void wprep(const float* __restrict__ W, fp16* __restrict__ Thi) {
    __shared__ float t[32][33];
    const int n0 = blockIdx.x * 32, k0 = blockIdx.y * 32;
    const int tx = threadIdx.x, ty = threadIdx.y;
    #pragma unroll
    for (int r = 0; r < 4; r++)
        t[ty + r * 8][tx] = W[(size_t)(k0 + ty + r * 8) * DM + n0 + tx];
    __syncthreads();
    #pragma unroll
    for (int r = 0; r < 4; r++) {
        const int nl = ty + r * 8;
        Thi[(size_t)(n0 + nl) * DM + k0 + tx] = __float2half_rn(t[tx][nl]);
    }
}

// ------------------------- mma.sync GEMM (fp16 2-term) -----------------------
#define ROWB 80
#define BUFB (128 * ROWB)
#define STAGEB (3 * BUFB)
#define TG_SMEM (2 * STAGEB)

__global__ __launch_bounds__(256, 1)
void tgemm(const fp16* __restrict__ Ahi, const fp16* __restrict__ Alo,
           const fp16* __restrict__ Bh, float* __restrict__ Cf,
           fp16* __restrict__ Chi, fp16* __restrict__ Clo,
           const float* __restrict__ resid, int N, int K)
{
    extern __shared__ __align__(128) char sb[];
    const uint32_t smb = smem_u32(sb);
    const int tid = threadIdx.x, lane = tid & 31, wid = tid >> 5;
    const int bm = blockIdx.y * 128, bn = blockIdx.x * 128;
    const int wm = (wid >> 2) * 64, wn = (wid & 3) * 32;

    uint32_t ldSm[6]; const fp16* ldG[6];
    #pragma unroll
    for (int i = 0; i < 6; i++) {
        const int buf = i >> 1;
        const int chunk = tid + (i & 1) * 256;
        const int r = chunk >> 2, j = chunk & 3;
        ldSm[i] = smb + buf * BUFB + r * ROWB + j * 16;
        const fp16* base = (buf == 0) ? Ahi : (buf == 1) ? Alo : Bh;
        const int rowg = (buf < 2) ? (bm + r) : (bn + r);
        ldG[i] = base + (size_t)rowg * K + j * 8;
    }

    const uint32_t aOff = (uint32_t)((wm + (lane & 15)) * ROWB + (((lane >> 4) << 3)) * 2);
    const uint32_t bOff = (uint32_t)((wn + ((lane >> 4) << 3) + (lane & 7)) * ROWB
                                     + ((((lane >> 3) & 1) << 3)) * 2);

    float acc[4][4][4] = {};
    const int NT = K / 32;

    #pragma unroll
    for (int i = 0; i < 6; i++) cp16(ldSm[i], ldG[i]);
    cp_commit();

    for (int t = 0; t < NT; t++) {
        if (t + 1 < NT) {
            const uint32_t so = ((t + 1) & 1) * STAGEB;
            const int kc = (t + 1) * 32;
            #pragma unroll
            for (int i = 0; i < 6; i++) cp16(ldSm[i] + so, ldG[i] + kc);
            cp_commit();
            cp_wait1();
        } else {
            cp_wait0();
        }
        __syncthreads();

        const uint32_t st = smb + (t & 1) * STAGEB;
        #pragma unroll
        for (int ks = 0; ks < 32; ks += 16) {
            uint32_t ah[4][4], al[4][4], bh2[2][4];
            #pragma unroll
            for (int mi = 0; mi < 4; mi++) {
                ldsm4(ah[mi], st + aOff + mi * (16 * ROWB) + ks * 2);
                ldsm4(al[mi], st + BUFB + aOff + mi * (16 * ROWB) + ks * 2);
            }
            #pragma unroll
            for (int n2 = 0; n2 < 2; n2++)
                ldsm4(bh2[n2], st + 2 * BUFB + bOff + n2 * (16 * ROWB) + ks * 2);
            #pragma unroll
            for (int mi = 0; mi < 4; mi++)
                #pragma unroll
                for (int ni = 0; ni < 4; ni++) {
                    const uint32_t* bp = &bh2[ni >> 1][(ni & 1) * 2];
                    mma16816(acc[mi][ni], ah[mi], bp);
                    mma16816(acc[mi][ni], al[mi], bp);
                }
        }
        __syncthreads();
    }

    #pragma unroll
    for (int mi = 0; mi < 4; mi++)
        #pragma unroll
        for (int ni = 0; ni < 4; ni++) {
            #pragma unroll
            for (int half = 0; half < 2; half++) {
                const int r = bm + wm + mi * 16 + (lane >> 2) + half * 8;
                const int c = bn + wn + ni * 8 + (lane & 3) * 2;
                const size_t idx = (size_t)r * N + c;
                float d0 = acc[mi][ni][half * 2 + 0];
                float d1 = acc[mi][ni][half * 2 + 1];
                if (resid) {
                    const float2 q2 = *reinterpret_cast<const float2*>(&resid[idx]);
                    d0 += q2.x; d1 += q2.y;
                }
                if (Cf) *reinterpret_cast<float2*>(&Cf[idx]) = make_float2(d0, d1);
                if (Chi) {
                    __half2 h, l;
                    split_pair(d0, d1, &h, &l);
                    *reinterpret_cast<__half2*>(&Chi[idx]) = h;
                    if (Clo) *reinterpret_cast<__half2*>(&Clo[idx]) = l;
                }
            }
        }
}

// ------------------------- S = Q K^T + inline mask + flag --------------------
#define ROWS_S 144
#define BUFS (128 * ROWS_S)
#define SROW 132
#define SA_SMEM (128 * SROW * 4)

__global__ __launch_bounds__(256, 1)
void sgemm_attn(const fp16* __restrict__ Ahi, const fp16* __restrict__ Alo,
                const fp16* __restrict__ Bh,
                const int* __restrict__ mask, float* __restrict__ attn)
{
    extern __shared__ __align__(128) char sb[];
    const uint32_t smb = smem_u32(sb);
    float* Ssm = reinterpret_cast<float*>(sb);
    const int tid = threadIdx.x, lane = tid & 31, wid = tid >> 5;
    const int k0t = blockIdx.x * 128;
    const int q0 = blockIdx.y * 128;
    const int bh = blockIdx.z;
    const int b = bh >> 4, h = bh & 15;
    const size_t hoff = (size_t)h * DK;
    const int wm = (wid >> 2) * 64, wn = (wid & 3) * 32;

    #pragma unroll
    for (int i = 0; i < 12; i++) {
        const int buf = i >> 2;
        const int chunk = tid + (i & 3) * 256;
        const int r = chunk >> 3, j = chunk & 7;
        const fp16* base = (buf == 0) ? Ahi : (buf == 1) ? Alo : Bh;
        const int rowg = (buf < 2) ? (b * SS + q0 + r) : (b * SS + k0t + r);
        cp16(smb + buf * BUFS + r * ROWS_S + j * 16,
             base + (size_t)rowg * DM + hoff + j * 8);
    }
    cp_commit();

    const uint32_t aOff = (uint32_t)((wm + (lane & 15)) * ROWS_S + (((lane >> 4) << 3)) * 2);
    const uint32_t bOff = (uint32_t)((wn + ((lane >> 4) << 3) + (lane & 7)) * ROWS_S
                                     + ((((lane >> 3) & 1) << 3)) * 2);

    cp_wait0();
    __syncthreads();

    float acc[4][4][4] = {};
    #pragma unroll
    for (int ks = 0; ks < 64; ks += 16) {
        uint32_t ah[4][4], al[4][4], bh2[2][4];
        #pragma unroll
        for (int mi = 0; mi < 4; mi++) {
            ldsm4(ah[mi], smb + aOff + mi * (16 * ROWS_S) + ks * 2);
            ldsm4(al[mi], smb + BUFS + aOff + mi * (16 * ROWS_S) + ks * 2);
        }
        #pragma unroll
        for (int n2 = 0; n2 < 2; n2++)
            ldsm4(bh2[n2], smb + 2 * BUFS + bOff + n2 * (16 * ROWS_S) + ks * 2);
        #pragma unroll
        for (int mi = 0; mi < 4; mi++)
            #pragma unroll
            for (int ni = 0; ni < 4; ni++) {
                const uint32_t* bp = &bh2[ni >> 1][(ni & 1) * 2];
                mma16816(acc[mi][ni], ah[mi], bp);
                mma16816(acc[mi][ni], al[mi], bp);
            }
    }

    // stage S tile to smem (inputs fully consumed)
    __syncthreads();
    #pragma unroll
    for (int mi = 0; mi < 4; mi++)
        #pragma unroll
        for (int ni = 0; ni < 4; ni++) {
            #pragma unroll
            for (int half = 0; half < 2; half++) {
                const int r = wm + mi * 16 + (lane >> 2) + half * 8;
                const int c = wn + ni * 8 + (lane & 3) * 2;
                *reinterpret_cast<float2*>(&Ssm[r * SROW + c]) =
                    make_float2(acc[mi][ni][half * 2 + 0],
                                acc[mi][ni][half * 2 + 1]);
            }
        }
    __syncthreads();

    // coalesced streaming writes with inline mask + all-ones flag
    int bad = 0;
    #pragma unroll
    for (int p = 0; p < 16; p++) {
        const int chunk = tid + p * 256;
        const int r = chunk >> 5, c4 = (chunk & 31) * 4;
        float4 v = *reinterpret_cast<const float4*>(&Ssm[r * SROW + c4]);
        const size_t grow = (size_t)(q0 + r);
        const int4 m = __ldcs(reinterpret_cast<const int4*>(
            &mask[((size_t)b * SS + grow) * SS + k0t + c4]));
        if (m.x == 0) { v.x = -1e9f; bad = 1; }
        if (m.y == 0) { v.y = -1e9f; bad = 1; }
        if (m.z == 0) { v.z = -1e9f; bad = 1; }
        if (m.w == 0) { v.w = -1e9f; bad = 1; }
        __stcs(reinterpret_cast<float4*>(
                   &attn[((size_t)bh * SS + grow) * SS + k0t + c4]), v);
    }
    if (__syncthreads_or(bad)) {
        if (tid == 0) atomicExch(&g_flag, 0);
    }
}

// ------------------------- P = K^T V (64x64 per bh), split-K -----------------
__global__ __launch_bounds__(256)
void pk_kernel()
{
    if (g_flag == 0) return;
    __shared__ float Ks[32][68];
    __shared__ float Vs[32][68];
    const int bh = blockIdx.x, split = blockIdx.y;
    const int b = bh >> 4, h = bh & 15;
    const size_t hoff = (size_t)h * DK;
    const int tid = threadIdx.x;
    const int tx = tid & 15, ty = tid >> 4;
    const __half2* khh = reinterpret_cast<const __half2*>(g_kh_hi);
    const __half2* khl = reinterpret_cast<const __half2*>(g_kh_lo);
    const __half2* vhh = reinterpret_cast<const __half2*>(g_vh_hi);
    const __half2* vhl = reinterpret_cast<const __half2*>(g_vh_lo);
    float acc[4][4] = {};
    for (int it = 0; it < 8; it++) {
        const int s0 = split * 256 + it * 32;
        __syncthreads();
        #pragma unroll
        for (int t = 0; t < 2; t++) {
            const int idx = tid + t * 256;
            const int rr = idx >> 4, c4 = idx & 15;
            const size_t g2 = ((size_t)(b * SS + s0 + rr) * DM + hoff) / 2 + c4 * 2;
            float2 kh0 = __half22float2(khh[g2]),     kl0 = __half22float2(khl[g2]);
            float2 kh1 = __half22float2(khh[g2 + 1]), kl1 = __half22float2(khl[g2 + 1]);
            Ks[rr][c4 * 4 + 0] = kh0.x + kl0.x; Ks[rr][c4 * 4 + 1] = kh0.y + kl0.y;
            Ks[rr][c4 * 4 + 2] = kh1.x + kl1.x; Ks[rr][c4 * 4 + 3] = kh1.y + kl1.y;
            float2 vh0 = __half22float2(vhh[g2]),     vl0 = __half22float2(vhl[g2]);
            float2 vh1 = __half22float2(vhh[g2 + 1]), vl1 = __half22float2(vhl[g2 + 1]);
            Vs[rr][c4 * 4 + 0] = vh0.x + vl0.x; Vs[rr][c4 * 4 + 1] = vh0.y + vl0.y;
            Vs[rr][c4 * 4 + 2] = vh1.x + vl1.x; Vs[rr][c4 * 4 + 3] = vh1.y + vl1.y;
        }
        __syncthreads();
        #pragma unroll 4
        for (int s = 0; s < 32; s++) {
            const float4 vv = *reinterpret_cast<const float4*>(&Vs[s][tx * 4]);
            #pragma unroll
            for (int i = 0; i < 4; i++) {
                const float kv = Ks[s][ty * 4 + i];
                acc[i][0] += kv * vv.x; acc[i][1] += kv * vv.y;
                acc[i][2] += kv * vv.z; acc[i][3] += kv * vv.w;
            }
        }
    }
    #pragma unroll
    for (int i = 0; i < 4; i++)
        #pragma unroll
        for (int j = 0; j < 4; j++)
            atomicAdd(&g_P[bh * (DK * DK) + (ty * 4 + i) * DK + tx * 4 + j], acc[i][j]);
}

// ------------------------- O = Qs @ P (fast path) ----------------------------
__global__ __launch_bounds__(256)
void ofast_kernel()
{
    if (g_flag == 0) return;
    __shared__ float Qs[64][68];
    __shared__ float Ps[64][64];
    const int q0 = blockIdx.x * 64;
    const int bh = blockIdx.y;
    const int b = bh >> 4, h = bh & 15;
    const size_t hoff = (size_t)h * DK;
    const int tid = threadIdx.x;
    const int tx = tid & 15, ty = tid >> 4;
    const __half2* qhh = reinterpret_cast<const __half2*>(g_qh_hi);
    const __half2* qhl = reinterpret_cast<const __half2*>(g_qh_lo);
    #pragma unroll
    for (int t = 0; t < 4; t++) {
        const int idx = tid + t * 256;
        const int rr = idx >> 4, c4 = idx & 15;
        const size_t g2 = ((size_t)(b * SS + q0 + rr) * DM + hoff) / 2 + c4 * 2;
        float2 h0 = __half22float2(qhh[g2]),     l0 = __half22float2(qhl[g2]);
        float2 h1 = __half22float2(qhh[g2 + 1]), l1 = __half22float2(qhl[g2 + 1]);
        Qs[rr][c4 * 4 + 0] = h0.x + l0.x; Qs[rr][c4 * 4 + 1] = h0.y + l0.y;
        Qs[rr][c4 * 4 + 2] = h1.x + l1.x; Qs[rr][c4 * 4 + 3] = h1.y + l1.y;
        *reinterpret_cast<float4*>(&Ps[rr][c4 * 4]) =
            reinterpret_cast<const float4*>(g_P)[(size_t)bh * (DK * DK) / 4 + rr * 16 + c4];
    }
    __syncthreads();
    float acc[4][4] = {};
    #pragma unroll 8
    for (int d = 0; d < 64; d++) {
        const float4 pv = *reinterpret_cast<const float4*>(&Ps[d][tx * 4]);
        #pragma unroll
        for (int i = 0; i < 4; i++) {
            const float qv = Qs[ty * 4 + i][d];
            acc[i][0] += qv * pv.x; acc[i][1] += qv * pv.y;
            acc[i][2] += qv * pv.z; acc[i][3] += qv * pv.w;
        }
    }
    #pragma unroll
    for (int i = 0; i < 4; i++) {
        const size_t base = (size_t)(b * SS + q0 + ty * 4 + i) * DM + hoff + tx * 4;
        __half2 h0, l0, h1, l1;
        split_pair(acc[i][0], acc[i][1], &h0, &l0);
        split_pair(acc[i][2], acc[i][3], &h1, &l1);
        __half2* ph = reinterpret_cast<__half2*>(&g_oh_hi[base]);
        __half2* pl = reinterpret_cast<__half2*>(&g_oh_lo[base]);
        ph[0] = h0; ph[1] = h1;
        pl[0] = l0; pl[1] = l1;
    }
}

// ------------------------- O = attn @ V (fallback) ---------------------------
__global__ __launch_bounds__(256)
void ofb_kernel(const float* __restrict__ attn)
{
    if (g_flag != 0) return;
    __shared__ float As[64][68];
    __shared__ float Vs[64][68];
    const int q0 = blockIdx.x * 64;
    const int bh = blockIdx.y;
    const int b = bh >> 4, h = bh & 15;
    const size_t hoff = (size_t)h * DK;
    const int tid = threadIdx.x;
    const int tx = tid & 15, ty = tid >> 4;
    const __half2* vhh = reinterpret_cast<const __half2*>(g_vh_hi);
    const __half2* vhl = reinterpret_cast<const __half2*>(g_vh_lo);
    float acc[4][4] = {};
    for (int k0 = 0; k0 < SS; k0 += 64) {
        __syncthreads();
        #pragma unroll
        for (int t = 0; t < 4; t++) {
            const int idx = tid + t * 256;
            const int rr = idx >> 4, c4 = idx & 15;
            *reinterpret_cast<float4*>(&As[rr][c4 * 4]) =
                reinterpret_cast<const float4*>(attn)[(((size_t)bh * SS + q0 + rr) * SS + k0) / 4 + c4];
            const size_t g2 = ((size_t)(b * SS + k0 + rr) * DM + hoff) / 2 + c4 * 2;
            float2 h0 = __half22float2(vhh[g2]),     l0 = __half22float2(vhl[g2]);
            float2 h1 = __half22float2(vhh[g2 + 1]), l1 = __half22float2(vhl[g2 + 1]);
            Vs[rr][c4 * 4 + 0] = h0.x + l0.x; Vs[rr][c4 * 4 + 1] = h0.y + l0.y;
            Vs[rr][c4 * 4 + 2] = h1.x + l1.x; Vs[rr][c4 * 4 + 3] = h1.y + l1.y;
        }
        __syncthreads();
        #pragma unroll 8
        for (int kk = 0; kk < 64; kk++) {
            const float4 vv = *reinterpret_cast<const float4*>(&Vs[kk][tx * 4]);
            #pragma unroll
            for (int i = 0; i < 4; i++) {
                const float sv = As[ty * 4 + i][kk];
                acc[i][0] += sv * vv.x; acc[i][1] += sv * vv.y;
                acc[i][2] += sv * vv.z; acc[i][3] += sv * vv.w;
            }
        }
    }
    #pragma unroll
    for (int i = 0; i < 4; i++) {
        const size_t base = (size_t)(b * SS + q0 + ty * 4 + i) * DM + hoff + tx * 4;
        __half2 h0, l0, h1, l1;
        split_pair(acc[i][0], acc[i][1], &h0, &l0);
        split_pair(acc[i][2], acc[i][3], &h1, &l1);
        __half2* ph = reinterpret_cast<__half2*>(&g_oh_hi[base]);
        __half2* pl = reinterpret_cast<__half2*>(&g_oh_lo[base]);
        ph[0] = h0; ph[1] = h1;
        pl[0] = l0; pl[1] = l1;
    }
}

// ---------------------------------------------------------------------------
extern "C" void kernel_launch(void* const* d_in, const int* in_sizes, int n_in,
                              void* d_out, int out_size)
{
    const float* q     = (const float*)d_in[0];
    const float* k     = (const float*)d_in[1];
    const float* v     = (const float*)d_in[2];
    const int*   mask  = (const int*)  d_in[3];
    const float* Wq    = (const float*)d_in[4];
    const float* Wk    = (const float*)d_in[5];
    const float* Wv    = (const float*)d_in[6];
    const float* Wfc   = (const float*)d_in[7];
    const float* gamma = (const float*)d_in[8];
    const float* beta  = (const float*)d_in[9];
    float* out = (float*)d_out;
    float* attn = ((long long)out_size >= (long long)OUT_ELEMS + ATTN_ELEMS)
                      ? out + OUT_ELEMS : nullptr;

    void* p;
    #define SYM(T, name, sym) cudaGetSymbolAddress(&p, sym); T* name = (T*)p
    SYM(fp16, qn_hi, g_qn_hi); SYM(fp16, qn_lo, g_qn_lo);
    SYM(fp16, ki_hi, g_ki_hi); SYM(fp16, ki_lo, g_ki_lo);
    SYM(fp16, vi_hi, g_vi_hi); SYM(fp16, vi_lo, g_vi_lo);
    SYM(fp16, wq_hi, g_wq_hi);
    SYM(fp16, wk_hi, g_wk_hi);
    SYM(fp16, wv_hi, g_wv_hi);
    SYM(fp16, wf_hi, g_wf_hi);
    SYM(fp16, qh_hi, g_qh_hi); SYM(fp16, qh_lo, g_qh_lo);
    SYM(fp16, kh_hi, g_kh_hi); SYM(fp16, kh_lo, g_kh_lo);
    SYM(fp16, vh_hi, g_vh_hi); SYM(fp16, vh_lo, g_vh_lo);
    SYM(fp16, oh_hi, g_oh_hi); SYM(fp16, oh_lo, g_oh_lo);
    #undef SYM

    cudaFuncSetAttribute(tgemm, cudaFuncAttributeMaxDynamicSharedMemorySize, TG_SMEM);
    cudaFuncSetAttribute(sgemm_attn, cudaFuncAttributeMaxDynamicSharedMemorySize, SA_SMEM);

    // prep
    initk<<<512, 256>>>();
    if (!attn) maskchk<<<2048, 256>>>(mask);
    ln_kernel<<<NROWS, 256>>>(q, gamma, beta, qn_hi, qn_lo);
    splitk<<<NROWS * DM / 4 / 256, 256>>>(k, ki_hi, ki_lo, NROWS * DM / 4);
    splitk<<<NROWS * DM / 4 / 256, 256>>>(v, vi_hi, vi_lo, NROWS * DM / 4);
    dim3 wg(32, 32), wb(32, 8);
    wprep<<<wg, wb>>>(Wq, wq_hi);
    wprep<<<wg, wb>>>(Wk, wk_hi);
    wprep<<<wg, wb>>>(Wv, wv_hi);
    wprep<<<wg, wb>>>(Wfc, wf_hi);

    // projections (fp16 2-term mma.sync)
    dim3 gg(DM / 128, NROWS / 128);
    tgemm<<<gg, 256, TG_SMEM>>>(qn_hi, qn_lo, wq_hi,
                                nullptr, qh_hi, qh_lo, nullptr, DM, DM);
    tgemm<<<gg, 256, TG_SMEM>>>(ki_hi, ki_lo, wk_hi,
                                nullptr, kh_hi, kh_lo, nullptr, DM, DM);
    tgemm<<<gg, 256, TG_SMEM>>>(vi_hi, vi_lo, wv_hi,
                                nullptr, vh_hi, vh_lo, nullptr, DM, DM);

    // attn scores + inline mask + all-ones flag
    if (attn)
        sgemm_attn<<<dim3(SS / 128, SS / 128, BB * NH), 256, SA_SMEM>>>(
            qh_hi, qh_lo, kh_hi, mask, attn);

    // O: fast path (mask all-ones) or fallback
    pk_kernel<<<dim3(BB * NH, 8), 256>>>();
    ofast_kernel<<<dim3(SS / 64, BB * NH), 256>>>();
    if (attn)
        ofb_kernel<<<dim3(SS / 64, BB * NH), 256>>>(attn);

    // fc + residual
    tgemm<<<gg, 256, TG_SMEM>>>(oh_hi, oh_lo, wf_hi,
                                out, nullptr, nullptr, q, DM, DM);
}

// round 9
// speedup vs baseline: 1.1837x; 1.1837x over previous
#include <cuda_runtime.h>
#include <cuda_fp16.h>
#include <cstdint>

#define BB 2
#define SS 2048
#define DM 1024
#define NH 16
#define DK 64
#define NROWS (BB * SS)
#define OUT_ELEMS (NROWS * DM)
#define ATTN_ELEMS (2LL * 16 * 2048 * 2048)
#define INV_TEMP 0.35355339059327373f

typedef __half fp16;

// ------------------------- device scratch (no allocs) -----------------------
__device__ __align__(128) fp16  g_qn_hi[NROWS * DM], g_qn_lo[NROWS * DM];
__device__ __align__(128) fp16  g_ki_hi[NROWS * DM], g_ki_lo[NROWS * DM];
__device__ __align__(128) fp16  g_vi_hi[NROWS * DM], g_vi_lo[NROWS * DM];
__device__ __align__(128) fp16  g_wq_hi[DM * DM];
__device__ __align__(128) fp16  g_wk_hi[DM * DM];
__device__ __align__(128) fp16  g_wv_hi[DM * DM];
__device__ __align__(128) fp16  g_wf_hi[DM * DM];
__device__ __align__(128) fp16  g_qh_hi[NROWS * DM], g_qh_lo[NROWS * DM];
__device__ __align__(128) fp16  g_kh_hi[NROWS * DM], g_kh_lo[NROWS * DM];
__device__ __align__(128) fp16  g_vh_hi[NROWS * DM], g_vh_lo[NROWS * DM];
__device__ __align__(128) fp16  g_oh_hi[NROWS * DM], g_oh_lo[NROWS * DM];
__device__ __align__(128) float g_P[BB * NH * DK * DK];
__device__ int g_flag;

// ------------------------- helpers ------------------------------------------
__device__ __forceinline__ uint32_t smem_u32(const void* p) {
    uint32_t a;
    asm("{ .reg .u64 t; cvta.to.shared.u64 t, %1; cvt.u32.u64 %0, t; }"
        : "=r"(a) : "l"(p));
    return a;
}
__device__ __forceinline__ void cp16(uint32_t saddr, const void* g) {
    asm volatile("cp.async.cg.shared.global [%0], [%1], 16;"
                 :: "r"(saddr), "l"(g) : "memory");
}
__device__ __forceinline__ void cp_commit() {
    asm volatile("cp.async.commit_group;" ::: "memory");
}
__device__ __forceinline__ void cp_wait0() {
    asm volatile("cp.async.wait_group 0;" ::: "memory");
}
__device__ __forceinline__ void cp_wait1() {
    asm volatile("cp.async.wait_group 1;" ::: "memory");
}
__device__ __forceinline__ void ldsm4(uint32_t* r, uint32_t addr) {
    asm volatile("ldmatrix.sync.aligned.m8n8.x4.shared.b16 {%0,%1,%2,%3}, [%4];"
                 : "=r"(r[0]), "=r"(r[1]), "=r"(r[2]), "=r"(r[3]) : "r"(addr));
}
__device__ __forceinline__ void mma16816(float* d, const uint32_t* a,
                                         const uint32_t* b) {
    asm volatile(
        "mma.sync.aligned.m16n8k16.row.col.f32.f16.f16.f32 "
        "{%0,%1,%2,%3}, {%4,%5,%6,%7}, {%8,%9}, {%0,%1,%2,%3};"
        : "+f"(d[0]), "+f"(d[1]), "+f"(d[2]), "+f"(d[3])
        : "r"(a[0]), "r"(a[1]), "r"(a[2]), "r"(a[3]), "r"(b[0]), "r"(b[1]));
}
__device__ __forceinline__ void split_pair(float x, float y, __half2* hi,
                                           __half2* lo) {
    __half2 h = __floats2half2_rn(x, y);
    *hi = h;
    *lo = __floats2half2_rn(x - __half2float(__low2half(h)),
                            y - __half2float(__high2half(h)));
}

// ------------------------- small prep kernels --------------------------------
__global__ void initk() {
    int i = blockIdx.x * 256 + threadIdx.x;
    if (i < BB * NH * DK * DK) g_P[i] = 0.0f;
    if (i == 0) g_flag = 1;
}

// fallback full-mask check (only used when attn buffer absent)
__global__ void maskchk(const int* __restrict__ mask) {
    const int4* m4 = reinterpret_cast<const int4*>(mask);
    const size_t total = (size_t)BB * SS * SS / 4;
    size_t i = (size_t)blockIdx.x * 256 + threadIdx.x;
    size_t stride = (size_t)gridDim.x * 256;
    int bad = 0;
    for (size_t j = i; j < total; j += stride) {
        int4 m = __ldcs(&m4[j]);
        if (!(m.x && m.y && m.z && m.w)) bad = 1;
    }
    if (bad) g_flag = 0;
}

__global__ void ln_kernel(const float* __restrict__ q,
                          const float* __restrict__ gamma,
                          const float* __restrict__ beta,
                          fp16* __restrict__ out_hi, fp16* __restrict__ out_lo) {
    __shared__ float red[16];
    const int row = blockIdx.x;
    const int tid = threadIdx.x;
    const float4 v = reinterpret_cast<const float4*>(q)[row * 256 + tid];
    float s  = v.x + v.y + v.z + v.w;
    float s2 = v.x * v.x + v.y * v.y + v.z * v.z + v.w * v.w;
    #pragma unroll
    for (int o = 16; o > 0; o >>= 1) {
        s  += __shfl_xor_sync(0xffffffffu, s,  o);
        s2 += __shfl_xor_sync(0xffffffffu, s2, o);
    }
    if ((tid & 31) == 0) { red[tid >> 5] = s; red[8 + (tid >> 5)] = s2; }
    __syncthreads();
    if (tid < 32) {
        s  = (tid < 8) ? red[tid]     : 0.0f;
        s2 = (tid < 8) ? red[8 + tid] : 0.0f;
        #pragma unroll
        for (int o = 4; o > 0; o >>= 1) {
            s  += __shfl_xor_sync(0xffffffffu, s,  o);
            s2 += __shfl_xor_sync(0xffffffffu, s2, o);
        }
        if (tid == 0) { red[0] = s; red[8] = s2; }
    }
    __syncthreads();
    const float mu   = red[0] * (1.0f / 1024.0f);
    const float var  = red[8] * (1.0f / 1024.0f) - mu * mu;
    const float rstd = rsqrtf(var + 1e-6f);
    const float4 g  = reinterpret_cast<const float4*>(gamma)[tid];
    const float4 bb = reinterpret_cast<const float4*>(beta)[tid];
    float y0 = ((v.x - mu) * rstd * g.x + bb.x) * INV_TEMP;
    float y1 = ((v.y - mu) * rstd * g.y + bb.y) * INV_TEMP;
    float y2 = ((v.z - mu) * rstd * g.z + bb.z) * INV_TEMP;
    float y3 = ((v.w - mu) * rstd * g.w + bb.w) * INV_TEMP;
    __half2 h0, l0, h1, l1;
    split_pair(y0, y1, &h0, &l0);
    split_pair(y2, y3, &h1, &l1);
    __half2* oh = reinterpret_cast<__half2*>(out_hi);
    __half2* ol = reinterpret_cast<__half2*>(out_lo);
    const int b2 = (row * 256 + tid) * 2;
    oh[b2] = h0; oh[b2 + 1] = h1;
    ol[b2] = l0; ol[b2 + 1] = l1;
}

__global__ void splitk(const float* __restrict__ x, fp16* __restrict__ hi,
                       fp16* __restrict__ lo, int n4) {
    int i = blockIdx.x * 256 + threadIdx.x;
    if (i >= n4) return;
    float4 v = reinterpret_cast<const float4*>(x)[i];
    __half2 h0, l0, h1, l1;
    split_pair(v.x, v.y, &h0, &l0);
    split_pair(v.z, v.w, &h1, &l1);
    reinterpret_cast<__half2*>(hi)[i * 2]     = h0;
    reinterpret_cast<__half2*>(hi)[i * 2 + 1] = h1;
    reinterpret_cast<__half2*>(lo)[i * 2]     = l0;
    reinterpret_cast<__half2*>(lo)[i * 2 + 1] = l1;
}

// W[K][N] -> WT[n][k] hi fp16 (transpose)
__global__ void wprep(const float* __restrict__ W, fp16* __restrict__ Thi) {
    __shared__ float t[32][33];
    const int n0 = blockIdx.x * 32, k0 = blockIdx.y * 32;
    const int tx = threadIdx.x, ty = threadIdx.y;
    #pragma unroll
    for (int r = 0; r < 4; r++)
        t[ty + r * 8][tx] = W[(size_t)(k0 + ty + r * 8) * DM + n0 + tx];
    __syncthreads();
    #pragma unroll
    for (int r = 0; r < 4; r++) {
        const int nl = ty + r * 8;
        Thi[(size_t)(n0 + nl) * DM + k0 + tx] = __float2half_rn(t[tx][nl]);
    }
}

// ------------------------- mma.sync GEMM (fp16 2-term) -----------------------
#define ROWB 80
#define BUFB (128 * ROWB)
#define STAGEB (3 * BUFB)
#define TG_SMEM (2 * STAGEB)

__global__ __launch_bounds__(256, 1)
void tgemm(const fp16* __restrict__ Ahi, const fp16* __restrict__ Alo,
           const fp16* __restrict__ Bh, float* __restrict__ Cf,
           fp16* __restrict__ Chi, fp16* __restrict__ Clo,
           const float* __restrict__ resid, int N, int K)
{
    extern __shared__ __align__(128) char sb[];
    const uint32_t smb = smem_u32(sb);
    const int tid = threadIdx.x, lane = tid & 31, wid = tid >> 5;
    const int bm = blockIdx.y * 128, bn = blockIdx.x * 128;
    const int wm = (wid >> 2) * 64, wn = (wid & 3) * 32;

    uint32_t ldSm[6]; const fp16* ldG[6];
    #pragma unroll
    for (int i = 0; i < 6; i++) {
        const int buf = i >> 1;
        const int chunk = tid + (i & 1) * 256;
        const int r = chunk >> 2, j = chunk & 3;
        ldSm[i] = smb + buf * BUFB + r * ROWB + j * 16;
        const fp16* base = (buf == 0) ? Ahi : (buf == 1) ? Alo : Bh;
        const int rowg = (buf < 2) ? (bm + r) : (bn + r);
        ldG[i] = base + (size_t)rowg * K + j * 8;
    }

    const uint32_t aOff = (uint32_t)((wm + (lane & 15)) * ROWB + (((lane >> 4) << 3)) * 2);
    const uint32_t bOff = (uint32_t)((wn + ((lane >> 4) << 3) + (lane & 7)) * ROWB
                                     + ((((lane >> 3) & 1) << 3)) * 2);

    float acc[4][4][4] = {};
    const int NT = K / 32;

    #pragma unroll
    for (int i = 0; i < 6; i++) cp16(ldSm[i], ldG[i]);
    cp_commit();

    for (int t = 0; t < NT; t++) {
        if (t + 1 < NT) {
            const uint32_t so = ((t + 1) & 1) * STAGEB;
            const int kc = (t + 1) * 32;
            #pragma unroll
            for (int i = 0; i < 6; i++) cp16(ldSm[i] + so, ldG[i] + kc);
            cp_commit();
            cp_wait1();
        } else {
            cp_wait0();
        }
        __syncthreads();

        const uint32_t st = smb + (t & 1) * STAGEB;
        #pragma unroll
        for (int ks = 0; ks < 32; ks += 16) {
            uint32_t ah[4][4], al[4][4], bh2[2][4];
            #pragma unroll
            for (int mi = 0; mi < 4; mi++) {
                ldsm4(ah[mi], st + aOff + mi * (16 * ROWB) + ks * 2);
                ldsm4(al[mi], st + BUFB + aOff + mi * (16 * ROWB) + ks * 2);
            }
            #pragma unroll
            for (int n2 = 0; n2 < 2; n2++)
                ldsm4(bh2[n2], st + 2 * BUFB + bOff + n2 * (16 * ROWB) + ks * 2);
            #pragma unroll
            for (int mi = 0; mi < 4; mi++)
                #pragma unroll
                for (int ni = 0; ni < 4; ni++) {
                    const uint32_t* bp = &bh2[ni >> 1][(ni & 1) * 2];
                    mma16816(acc[mi][ni], ah[mi], bp);
                    mma16816(acc[mi][ni], al[mi], bp);
                }
        }
        __syncthreads();
    }

    #pragma unroll
    for (int mi = 0; mi < 4; mi++)
        #pragma unroll
        for (int ni = 0; ni < 4; ni++) {
            #pragma unroll
            for (int half = 0; half < 2; half++) {
                const int r = bm + wm + mi * 16 + (lane >> 2) + half * 8;
                const int c = bn + wn + ni * 8 + (lane & 3) * 2;
                const size_t idx = (size_t)r * N + c;
                float d0 = acc[mi][ni][half * 2 + 0];
                float d1 = acc[mi][ni][half * 2 + 1];
                if (resid) {
                    const float2 q2 = *reinterpret_cast<const float2*>(&resid[idx]);
                    d0 += q2.x; d1 += q2.y;
                }
                if (Cf) *reinterpret_cast<float2*>(&Cf[idx]) = make_float2(d0, d1);
                if (Chi) {
                    __half2 h, l;
                    split_pair(d0, d1, &h, &l);
                    *reinterpret_cast<__half2*>(&Chi[idx]) = h;
                    if (Clo) *reinterpret_cast<__half2*>(&Clo[idx]) = l;
                }
            }
        }
}

// ------------------------- S = Q K^T + smem-prefetched mask ------------------
// inputs [0, 3*BUFS) -> reused by S stage [0, 128*SROW*4); mask tile at MOFF.
#define ROWS_S 144
#define BUFS (128 * ROWS_S)          // 18432; inputs end at 55296
#define SROW 132                     // S stage: 128*132*4 = 67584
#define MOFF 67584                   // mask tile: 64 KB
#define SA_SMEM (MOFF + 128 * 128 * 4)   // 133120

__global__ __launch_bounds__(256, 1)
void sgemm_attn(const fp16* __restrict__ Ahi, const fp16* __restrict__ Alo,
                const fp16* __restrict__ Bh,
                const int* __restrict__ mask, float* __restrict__ attn)
{
    extern __shared__ __align__(128) char sb[];
    const uint32_t smb = smem_u32(sb);
    float* Ssm = reinterpret_cast<float*>(sb);
    const int tid = threadIdx.x, lane = tid & 31, wid = tid >> 5;
    const int k0t = blockIdx.x * 128;
    const int q0 = blockIdx.y * 128;
    const int bh = blockIdx.z;
    const int b = bh >> 4, h = bh & 15;
    const size_t hoff = (size_t)h * DK;
    const int wm = (wid >> 2) * 64, wn = (wid & 3) * 32;

    // group A: Q/K inputs (12 x 16B per thread)
    #pragma unroll
    for (int i = 0; i < 12; i++) {
        const int buf = i >> 2;
        const int chunk = tid + (i & 3) * 256;
        const int r = chunk >> 3, j = chunk & 7;
        const fp16* base = (buf == 0) ? Ahi : (buf == 1) ? Alo : Bh;
        const int rowg = (buf < 2) ? (b * SS + q0 + r) : (b * SS + k0t + r);
        cp16(smb + buf * BUFS + r * ROWS_S + j * 16,
             base + (size_t)rowg * DM + hoff + j * 8);
    }
    cp_commit();

    // group B: mask tile (16 x 16B per thread), same chunk map as epilogue
    #pragma unroll
    for (int p = 0; p < 16; p++) {
        const int chunk = tid + p * 256;                 // 0..4095
        const int r = chunk >> 5, c4 = (chunk & 31) * 4;
        cp16(smb + MOFF + chunk * 16,
             &mask[((size_t)b * SS + q0 + r) * SS + k0t + c4]);
    }
    cp_commit();

    const uint32_t aOff = (uint32_t)((wm + (lane & 15)) * ROWS_S + (((lane >> 4) << 3)) * 2);
    const uint32_t bOff = (uint32_t)((wn + ((lane >> 4) << 3) + (lane & 7)) * ROWS_S
                                     + ((((lane >> 3) & 1) << 3)) * 2);

    cp_wait1();                      // inputs ready; mask still in flight
    __syncthreads();

    float acc[4][4][4] = {};
    #pragma unroll
    for (int ks = 0; ks < 64; ks += 16) {
        uint32_t ah[4][4], al[4][4], bh2[2][4];
        #pragma unroll
        for (int mi = 0; mi < 4; mi++) {
            ldsm4(ah[mi], smb + aOff + mi * (16 * ROWS_S) + ks * 2);
            ldsm4(al[mi], smb + BUFS + aOff + mi * (16 * ROWS_S) + ks * 2);
        }
        #pragma unroll
        for (int n2 = 0; n2 < 2; n2++)
            ldsm4(bh2[n2], smb + 2 * BUFS + bOff + n2 * (16 * ROWS_S) + ks * 2);
        #pragma unroll
        for (int mi = 0; mi < 4; mi++)
            #pragma unroll
            for (int ni = 0; ni < 4; ni++) {
                const uint32_t* bp = &bh2[ni >> 1][(ni & 1) * 2];
                mma16816(acc[mi][ni], ah[mi], bp);
                mma16816(acc[mi][ni], al[mi], bp);
            }
    }

    // stage S tile to smem (inputs fully consumed; mask region untouched)
    __syncthreads();
    #pragma unroll
    for (int mi = 0; mi < 4; mi++)
        #pragma unroll
        for (int ni = 0; ni < 4; ni++) {
            #pragma unroll
            for (int half = 0; half < 2; half++) {
                const int r = wm + mi * 16 + (lane >> 2) + half * 8;
                const int c = wn + ni * 8 + (lane & 3) * 2;
                *reinterpret_cast<float2*>(&Ssm[r * SROW + c]) =
                    make_float2(acc[mi][ni][half * 2 + 0],
                                acc[mi][ni][half * 2 + 1]);
            }
        }
    cp_wait0();                      // mask tile resident (self-fetched chunks)
    __syncthreads();

    // coalesced streaming writes; mask read from smem only
    int bad = 0;
    #pragma unroll
    for (int p = 0; p < 16; p++) {
        const int chunk = tid + p * 256;
        const int r = chunk >> 5, c4 = (chunk & 31) * 4;
        float4 v = *reinterpret_cast<const float4*>(&Ssm[r * SROW + c4]);
        const int4 m = *reinterpret_cast<const int4*>(sb + MOFF + chunk * 16);
        if (m.x == 0) { v.x = -1e9f; bad = 1; }
        if (m.y == 0) { v.y = -1e9f; bad = 1; }
        if (m.z == 0) { v.z = -1e9f; bad = 1; }
        if (m.w == 0) { v.w = -1e9f; bad = 1; }
        __stcs(reinterpret_cast<float4*>(
                   &attn[((size_t)bh * SS + q0 + r) * SS + k0t + c4]), v);
    }
    if (__syncthreads_or(bad)) {
        if (tid == 0) atomicExch(&g_flag, 0);
    }
}

// ------------------------- P = K^T V (64x64 per bh), split-K -----------------
__global__ __launch_bounds__(256)
void pk_kernel()
{
    if (g_flag == 0) return;
    __shared__ float Ks[32][68];
    __shared__ float Vs[32][68];
    const int bh = blockIdx.x, split = blockIdx.y;
    const int b = bh >> 4, h = bh & 15;
    const size_t hoff = (size_t)h * DK;
    const int tid = threadIdx.x;
    const int tx = tid & 15, ty = tid >> 4;
    const __half2* khh = reinterpret_cast<const __half2*>(g_kh_hi);
    const __half2* khl = reinterpret_cast<const __half2*>(g_kh_lo);
    const __half2* vhh = reinterpret_cast<const __half2*>(g_vh_hi);
    const __half2* vhl = reinterpret_cast<const __half2*>(g_vh_lo);
    float acc[4][4] = {};
    for (int it = 0; it < 8; it++) {
        const int s0 = split * 256 + it * 32;
        __syncthreads();
        #pragma unroll
        for (int t = 0; t < 2; t++) {
            const int idx = tid + t * 256;
            const int rr = idx >> 4, c4 = idx & 15;
            const size_t g2 = ((size_t)(b * SS + s0 + rr) * DM + hoff) / 2 + c4 * 2;
            float2 kh0 = __half22float2(khh[g2]),     kl0 = __half22float2(khl[g2]);
            float2 kh1 = __half22float2(khh[g2 + 1]), kl1 = __half22float2(khl[g2 + 1]);
            Ks[rr][c4 * 4 + 0] = kh0.x + kl0.x; Ks[rr][c4 * 4 + 1] = kh0.y + kl0.y;
            Ks[rr][c4 * 4 + 2] = kh1.x + kl1.x; Ks[rr][c4 * 4 + 3] = kh1.y + kl1.y;
            float2 vh0 = __half22float2(vhh[g2]),     vl0 = __half22float2(vhl[g2]);
            float2 vh1 = __half22float2(vhh[g2 + 1]), vl1 = __half22float2(vhl[g2 + 1]);
            Vs[rr][c4 * 4 + 0] = vh0.x + vl0.x; Vs[rr][c4 * 4 + 1] = vh0.y + vl0.y;
            Vs[rr][c4 * 4 + 2] = vh1.x + vl1.x; Vs[rr][c4 * 4 + 3] = vh1.y + vl1.y;
        }
        __syncthreads();
        #pragma unroll 4
        for (int s = 0; s < 32; s++) {
            const float4 vv = *reinterpret_cast<const float4*>(&Vs[s][tx * 4]);
            #pragma unroll
            for (int i = 0; i < 4; i++) {
                const float kv = Ks[s][ty * 4 + i];
                acc[i][0] += kv * vv.x; acc[i][1] += kv * vv.y;
                acc[i][2] += kv * vv.z; acc[i][3] += kv * vv.w;
            }
        }
    }
    #pragma unroll
    for (int i = 0; i < 4; i++)
        #pragma unroll
        for (int j = 0; j < 4; j++)
            atomicAdd(&g_P[bh * (DK * DK) + (ty * 4 + i) * DK + tx * 4 + j], acc[i][j]);
}

// ------------------------- O = Qs @ P (fast path) ----------------------------
__global__ __launch_bounds__(256)
void ofast_kernel()
{
    if (g_flag == 0) return;
    __shared__ float Qs[64][68];
    __shared__ float Ps[64][64];
    const int q0 = blockIdx.x * 64;
    const int bh = blockIdx.y;
    const int b = bh >> 4, h = bh & 15;
    const size_t hoff = (size_t)h * DK;
    const int tid = threadIdx.x;
    const int tx = tid & 15, ty = tid >> 4;
    const __half2* qhh = reinterpret_cast<const __half2*>(g_qh_hi);
    const __half2* qhl = reinterpret_cast<const __half2*>(g_qh_lo);
    #pragma unroll
    for (int t = 0; t < 4; t++) {
        const int idx = tid + t * 256;
        const int rr = idx >> 4, c4 = idx & 15;
        const size_t g2 = ((size_t)(b * SS + q0 + rr) * DM + hoff) / 2 + c4 * 2;
        float2 h0 = __half22float2(qhh[g2]),     l0 = __half22float2(qhl[g2]);
        float2 h1 = __half22float2(qhh[g2 + 1]), l1 = __half22float2(qhl[g2 + 1]);
        Qs[rr][c4 * 4 + 0] = h0.x + l0.x; Qs[rr][c4 * 4 + 1] = h0.y + l0.y;
        Qs[rr][c4 * 4 + 2] = h1.x + l1.x; Qs[rr][c4 * 4 + 3] = h1.y + l1.y;
        *reinterpret_cast<float4*>(&Ps[rr][c4 * 4]) =
            reinterpret_cast<const float4*>(g_P)[(size_t)bh * (DK * DK) / 4 + rr * 16 + c4];
    }
    __syncthreads();
    float acc[4][4] = {};
    #pragma unroll 8
    for (int d = 0; d < 64; d++) {
        const float4 pv = *reinterpret_cast<const float4*>(&Ps[d][tx * 4]);
        #pragma unroll
        for (int i = 0; i < 4; i++) {
            const float qv = Qs[ty * 4 + i][d];
            acc[i][0] += qv * pv.x; acc[i][1] += qv * pv.y;
            acc[i][2] += qv * pv.z; acc[i][3] += qv * pv.w;
        }
    }
    #pragma unroll
    for (int i = 0; i < 4; i++) {
        const size_t base = (size_t)(b * SS + q0 + ty * 4 + i) * DM + hoff + tx * 4;
        __half2 h0, l0, h1, l1;
        split_pair(acc[i][0], acc[i][1], &h0, &l0);
        split_pair(acc[i][2], acc[i][3], &h1, &l1);
        __half2* ph = reinterpret_cast<__half2*>(&g_oh_hi[base]);
        __half2* pl = reinterpret_cast<__half2*>(&g_oh_lo[base]);
        ph[0] = h0; ph[1] = h1;
        pl[0] = l0; pl[1] = l1;
    }
}

// ------------------------- O = attn @ V (fallback) ---------------------------
__global__ __launch_bounds__(256)
void ofb_kernel(const float* __restrict__ attn)
{
    if (g_flag != 0) return;
    __shared__ float As[64][68];
    __shared__ float Vs[64][68];
    const int q0 = blockIdx.x * 64;
    const int bh = blockIdx.y;
    const int b = bh >> 4, h = bh & 15;
    const size_t hoff = (size_t)h * DK;
    const int tid = threadIdx.x;
    const int tx = tid & 15, ty = tid >> 4;
    const __half2* vhh = reinterpret_cast<const __half2*>(g_vh_hi);
    const __half2* vhl = reinterpret_cast<const __half2*>(g_vh_lo);
    float acc[4][4] = {};
    for (int k0 = 0; k0 < SS; k0 += 64) {
        __syncthreads();
        #pragma unroll
        for (int t = 0; t < 4; t++) {
            const int idx = tid + t * 256;
            const int rr = idx >> 4, c4 = idx & 15;
            *reinterpret_cast<float4*>(&As[rr][c4 * 4]) =
                reinterpret_cast<const float4*>(attn)[(((size_t)bh * SS + q0 + rr) * SS + k0) / 4 + c4];
            const size_t g2 = ((size_t)(b * SS + k0 + rr) * DM + hoff) / 2 + c4 * 2;
            float2 h0 = __half22float2(vhh[g2]),     l0 = __half22float2(vhl[g2]);
            float2 h1 = __half22float2(vhh[g2 + 1]), l1 = __half22float2(vhl[g2 + 1]);
            Vs[rr][c4 * 4 + 0] = h0.x + l0.x; Vs[rr][c4 * 4 + 1] = h0.y + l0.y;
            Vs[rr][c4 * 4 + 2] = h1.x + l1.x; Vs[rr][c4 * 4 + 3] = h1.y + l1.y;
        }
        __syncthreads();
        #pragma unroll 8
        for (int kk = 0; kk < 64; kk++) {
            const float4 vv = *reinterpret_cast<const float4*>(&Vs[kk][tx * 4]);
            #pragma unroll
            for (int i = 0; i < 4; i++) {
                const float sv = As[ty * 4 + i][kk];
                acc[i][0] += sv * vv.x; acc[i][1] += sv * vv.y;
                acc[i][2] += sv * vv.z; acc[i][3] += sv * vv.w;
            }
        }
    }
    #pragma unroll
    for (int i = 0; i < 4; i++) {
        const size_t base = (size_t)(b * SS + q0 + ty * 4 + i) * DM + hoff + tx * 4;
        __half2 h0, l0, h1, l1;
        split_pair(acc[i][0], acc[i][1], &h0, &l0);
        split_pair(acc[i][2], acc[i][3], &h1, &l1);
        __half2* ph = reinterpret_cast<__half2*>(&g_oh_hi[base]);
        __half2* pl = reinterpret_cast<__half2*>(&g_oh_lo[base]);
        ph[0] = h0; ph[1] = h1;
        pl[0] = l0; pl[1] = l1;
    }
}

// ---------------------------------------------------------------------------
extern "C" void kernel_launch(void* const* d_in, const int* in_sizes, int n_in,
                              void* d_out, int out_size)
{
    const float* q     = (const float*)d_in[0];
    const float* k     = (const float*)d_in[1];
    const float* v     = (const float*)d_in[2];
    const int*   mask  = (const int*)  d_in[3];
    const float* Wq    = (const float*)d_in[4];
    const float* Wk    = (const float*)d_in[5];
    const float* Wv    = (const float*)d_in[6];
    const float* Wfc   = (const float*)d_in[7];
    const float* gamma = (const float*)d_in[8];
    const float* beta  = (const float*)d_in[9];
    float* out = (float*)d_out;
    float* attn = ((long long)out_size >= (long long)OUT_ELEMS + ATTN_ELEMS)
                      ? out + OUT_ELEMS : nullptr;

    void* p;
    #define SYM(T, name, sym) cudaGetSymbolAddress(&p, sym); T* name = (T*)p
    SYM(fp16, qn_hi, g_qn_hi); SYM(fp16, qn_lo, g_qn_lo);
    SYM(fp16, ki_hi, g_ki_hi); SYM(fp16, ki_lo, g_ki_lo);
    SYM(fp16, vi_hi, g_vi_hi); SYM(fp16, vi_lo, g_vi_lo);
    SYM(fp16, wq_hi, g_wq_hi);
    SYM(fp16, wk_hi, g_wk_hi);
    SYM(fp16, wv_hi, g_wv_hi);
    SYM(fp16, wf_hi, g_wf_hi);
    SYM(fp16, qh_hi, g_qh_hi); SYM(fp16, qh_lo, g_qh_lo);
    SYM(fp16, kh_hi, g_kh_hi); SYM(fp16, kh_lo, g_kh_lo);
    SYM(fp16, vh_hi, g_vh_hi); SYM(fp16, vh_lo, g_vh_lo);
    SYM(fp16, oh_hi, g_oh_hi); SYM(fp16, oh_lo, g_oh_lo);
    #undef SYM

    cudaFuncSetAttribute(tgemm, cudaFuncAttributeMaxDynamicSharedMemorySize, TG_SMEM);
    cudaFuncSetAttribute(sgemm_attn, cudaFuncAttributeMaxDynamicSharedMemorySize, SA_SMEM);

    // prep
    initk<<<512, 256>>>();
    if (!attn) maskchk<<<2048, 256>>>(mask);
    ln_kernel<<<NROWS, 256>>>(q, gamma, beta, qn_hi, qn_lo);
    splitk<<<NROWS * DM / 4 / 256, 256>>>(k, ki_hi, ki_lo, NROWS * DM / 4);
    splitk<<<NROWS * DM / 4 / 256, 256>>>(v, vi_hi, vi_lo, NROWS * DM / 4);
    dim3 wg(32, 32), wb(32, 8);
    wprep<<<wg, wb>>>(Wq, wq_hi);
    wprep<<<wg, wb>>>(Wk, wk_hi);
    wprep<<<wg, wb>>>(Wv, wv_hi);
    wprep<<<wg, wb>>>(Wfc, wf_hi);

    // projections (fp16 2-term mma.sync)
    dim3 gg(DM / 128, NROWS / 128);
    tgemm<<<gg, 256, TG_SMEM>>>(qn_hi, qn_lo, wq_hi,
                                nullptr, qh_hi, qh_lo, nullptr, DM, DM);
    tgemm<<<gg, 256, TG_SMEM>>>(ki_hi, ki_lo, wk_hi,
                                nullptr, kh_hi, kh_lo, nullptr, DM, DM);
    tgemm<<<gg, 256, TG_SMEM>>>(vi_hi, vi_lo, wv_hi,
                                nullptr, vh_hi, vh_lo, nullptr, DM, DM);

    // attn scores + smem-prefetched mask + all-ones flag
    if (attn)
        sgemm_attn<<<dim3(SS / 128, SS / 128, BB * NH), 256, SA_SMEM>>>(
            qh_hi, qh_lo, kh_hi, mask, attn);

    // O: fast path (mask all-ones) or fallback
    pk_kernel<<<dim3(BB * NH, 8), 256>>>();
    ofast_kernel<<<dim3(SS / 64, BB * NH), 256>>>();
    if (attn)
        ofb_kernel<<<dim3(SS / 64, BB * NH), 256>>>(attn);

    // fc + residual
    tgemm<<<gg, 256, TG_SMEM>>>(oh_hi, oh_lo, wf_hi,
                                out, nullptr, nullptr, q, DM, DM);
}

// round 11
// speedup vs baseline: 1.2772x; 1.0789x over previous
#include <cuda_runtime.h>
#include <cuda_fp16.h>
#include <cstdint>

#define BB 2
#define SS 2048
#define DM 1024
#define NH 16
#define DK 64
#define NROWS (BB * SS)
#define OUT_ELEMS (NROWS * DM)
#define ATTN_ELEMS (2LL * 16 * 2048 * 2048)
#define INV_TEMP 0.35355339059327373f

typedef __half fp16;

// ------------------------- device scratch (no allocs) -----------------------
__device__ __align__(128) fp16  g_qn_hi[NROWS * DM], g_qn_lo[NROWS * DM];
__device__ __align__(128) fp16  g_ki_hi[NROWS * DM], g_ki_lo[NROWS * DM];
__device__ __align__(128) fp16  g_vi_hi[NROWS * DM], g_vi_lo[NROWS * DM];
__device__ __align__(128) fp16  g_wq_hi[DM * DM];
__device__ __align__(128) fp16  g_wk_hi[DM * DM];
__device__ __align__(128) fp16  g_wv_hi[DM * DM];
__device__ __align__(128) fp16  g_wf_hi[DM * DM];
__device__ __align__(128) fp16  g_qh_hi[NROWS * DM], g_qh_lo[NROWS * DM];
__device__ __align__(128) fp16  g_kh_hi[NROWS * DM], g_kh_lo[NROWS * DM];
__device__ __align__(128) fp16  g_vh_hi[NROWS * DM], g_vh_lo[NROWS * DM];
__device__ __align__(128) fp16  g_oh_hi[NROWS * DM], g_oh_lo[NROWS * DM];
__device__ __align__(128) float g_P[BB * NH * DK * DK];
__device__ int g_flag;

// ------------------------- helpers ------------------------------------------
__device__ __forceinline__ uint32_t smem_u32(const void* p) {
    uint32_t a;
    asm("{ .reg .u64 t; cvta.to.shared.u64 t, %1; cvt.u32.u64 %0, t; }"
        : "=r"(a) : "l"(p));
    return a;
}
__device__ __forceinline__ void cp16(uint32_t saddr, const void* g) {
    asm volatile("cp.async.cg.shared.global [%0], [%1], 16;"
                 :: "r"(saddr), "l"(g) : "memory");
}
__device__ __forceinline__ void cp_commit() {
    asm volatile("cp.async.commit_group;" ::: "memory");
}
__device__ __forceinline__ void cp_wait0() {
    asm volatile("cp.async.wait_group 0;" ::: "memory");
}
__device__ __forceinline__ void cp_wait1() {
    asm volatile("cp.async.wait_group 1;" ::: "memory");
}
__device__ __forceinline__ void ldsm4(uint32_t* r, uint32_t addr) {
    asm volatile("ldmatrix.sync.aligned.m8n8.x4.shared.b16 {%0,%1,%2,%3}, [%4];"
                 : "=r"(r[0]), "=r"(r[1]), "=r"(r[2]), "=r"(r[3]) : "r"(addr));
}
__device__ __forceinline__ void mma16816(float* d, const uint32_t* a,
                                         const uint32_t* b) {
    asm volatile(
        "mma.sync.aligned.m16n8k16.row.col.f32.f16.f16.f32 "
        "{%0,%1,%2,%3}, {%4,%5,%6,%7}, {%8,%9}, {%0,%1,%2,%3};"
        : "+f"(d[0]), "+f"(d[1]), "+f"(d[2]), "+f"(d[3])
        : "r"(a[0]), "r"(a[1]), "r"(a[2]), "r"(a[3]), "r"(b[0]), "r"(b[1]));
}
__device__ __forceinline__ void split_pair(float x, float y, __half2* hi,
                                           __half2* lo) {
    __half2 h = __floats2half2_rn(x, y);
    *hi = h;
    *lo = __floats2half2_rn(x - __half2float(__low2half(h)),
                            y - __half2float(__high2half(h)));
}

// ------------------------- small prep kernels --------------------------------
__global__ void initk() {
    int i = blockIdx.x * 256 + threadIdx.x;
    if (i < BB * NH * DK * DK) g_P[i] = 0.0f;
    if (i == 0) g_flag = 1;
}

// fallback full-mask check (only used when attn buffer absent)
__global__ void maskchk(const int* __restrict__ mask) {
    const int4* m4 = reinterpret_cast<const int4*>(mask);
    const size_t total = (size_t)BB * SS * SS / 4;
    size_t i = (size_t)blockIdx.x * 256 + threadIdx.x;
    size_t stride = (size_t)gridDim.x * 256;
    int bad = 0;
    for (size_t j = i; j < total; j += stride) {
        int4 m = __ldcs(&m4[j]);
        if (!(m.x && m.y && m.z && m.w)) bad = 1;
    }
    if (bad) g_flag = 0;
}

__global__ void ln_kernel(const float* __restrict__ q,
                          const float* __restrict__ gamma,
                          const float* __restrict__ beta,
                          fp16* __restrict__ out_hi, fp16* __restrict__ out_lo) {
    __shared__ float red[16];
    const int row = blockIdx.x;
    const int tid = threadIdx.x;
    const float4 v = reinterpret_cast<const float4*>(q)[row * 256 + tid];
    float s  = v.x + v.y + v.z + v.w;
    float s2 = v.x * v.x + v.y * v.y + v.z * v.z + v.w * v.w;
    #pragma unroll
    for (int o = 16; o > 0; o >>= 1) {
        s  += __shfl_xor_sync(0xffffffffu, s,  o);
        s2 += __shfl_xor_sync(0xffffffffu, s2, o);
    }
    if ((tid & 31) == 0) { red[tid >> 5] = s; red[8 + (tid >> 5)] = s2; }
    __syncthreads();
    if (tid < 32) {
        s  = (tid < 8) ? red[tid]     : 0.0f;
        s2 = (tid < 8) ? red[8 + tid] : 0.0f;
        #pragma unroll
        for (int o = 4; o > 0; o >>= 1) {
            s  += __shfl_xor_sync(0xffffffffu, s,  o);
            s2 += __shfl_xor_sync(0xffffffffu, s2, o);
        }
        if (tid == 0) { red[0] = s; red[8] = s2; }
    }
    __syncthreads();
    const float mu   = red[0] * (1.0f / 1024.0f);
    const float var  = red[8] * (1.0f / 1024.0f) - mu * mu;
    const float rstd = rsqrtf(var + 1e-6f);
    const float4 g  = reinterpret_cast<const float4*>(gamma)[tid];
    const float4 bb = reinterpret_cast<const float4*>(beta)[tid];
    float y0 = ((v.x - mu) * rstd * g.x + bb.x) * INV_TEMP;
    float y1 = ((v.y - mu) * rstd * g.y + bb.y) * INV_TEMP;
    float y2 = ((v.z - mu) * rstd * g.z + bb.z) * INV_TEMP;
    float y3 = ((v.w - mu) * rstd * g.w + bb.w) * INV_TEMP;
    __half2 h0, l0, h1, l1;
    split_pair(y0, y1, &h0, &l0);
    split_pair(y2, y3, &h1, &l1);
    __half2* oh = reinterpret_cast<__half2*>(out_hi);
    __half2* ol = reinterpret_cast<__half2*>(out_lo);
    const int b2 = (row * 256 + tid) * 2;
    oh[b2] = h0; oh[b2 + 1] = h1;
    ol[b2] = l0; ol[b2 + 1] = l1;
}

__global__ void splitk(const float* __restrict__ x, fp16* __restrict__ hi,
                       fp16* __restrict__ lo, int n4) {
    int i = blockIdx.x * 256 + threadIdx.x;
    if (i >= n4) return;
    float4 v = reinterpret_cast<const float4*>(x)[i];
    __half2 h0, l0, h1, l1;
    split_pair(v.x, v.y, &h0, &l0);
    split_pair(v.z, v.w, &h1, &l1);
    reinterpret_cast<__half2*>(hi)[i * 2]     = h0;
    reinterpret_cast<__half2*>(hi)[i * 2 + 1] = h1;
    reinterpret_cast<__half2*>(lo)[i * 2]     = l0;
    reinterpret_cast<__half2*>(lo)[i * 2 + 1] = l1;
}

// W[K][N] -> WT[n][k] hi fp16 (transpose)
__global__ void wprep(const float* __restrict__ W, fp16* __restrict__ Thi) {
    __shared__ float t[32][33];
    const int n0 = blockIdx.x * 32, k0 = blockIdx.y * 32;
    const int tx = threadIdx.x, ty = threadIdx.y;
    #pragma unroll
    for (int r = 0; r < 4; r++)
        t[ty + r * 8][tx] = W[(size_t)(k0 + ty + r * 8) * DM + n0 + tx];
    __syncthreads();
    #pragma unroll
    for (int r = 0; r < 4; r++) {
        const int nl = ty + r * 8;
        Thi[(size_t)(n0 + nl) * DM + k0 + tx] = __float2half_rn(t[tx][nl]);
    }
}

// ------------------------- mma.sync GEMM (fp16 2-term) -----------------------
#define ROWB 80
#define BUFB (128 * ROWB)
#define STAGEB (3 * BUFB)
#define TG_SMEM (2 * STAGEB)

__global__ __launch_bounds__(256, 1)
void tgemm(const fp16* __restrict__ Ahi, const fp16* __restrict__ Alo,
           const fp16* __restrict__ Bh, float* __restrict__ Cf,
           fp16* __restrict__ Chi, fp16* __restrict__ Clo,
           const float* __restrict__ resid, int N, int K)
{
    extern __shared__ __align__(128) char sb[];
    const uint32_t smb = smem_u32(sb);
    const int tid = threadIdx.x, lane = tid & 31, wid = tid >> 5;
    const int bm = blockIdx.y * 128, bn = blockIdx.x * 128;
    const int wm = (wid >> 2) * 64, wn = (wid & 3) * 32;

    uint32_t ldSm[6]; const fp16* ldG[6];
    #pragma unroll
    for (int i = 0; i < 6; i++) {
        const int buf = i >> 1;
        const int chunk = tid + (i & 1) * 256;
        const int r = chunk >> 2, j = chunk & 3;
        ldSm[i] = smb + buf * BUFB + r * ROWB + j * 16;
        const fp16* base = (buf == 0) ? Ahi : (buf == 1) ? Alo : Bh;
        const int rowg = (buf < 2) ? (bm + r) : (bn + r);
        ldG[i] = base + (size_t)rowg * K + j * 8;
    }

    const uint32_t aOff = (uint32_t)((wm + (lane & 15)) * ROWB + (((lane >> 4) << 3)) * 2);
    const uint32_t bOff = (uint32_t)((wn + ((lane >> 4) << 3) + (lane & 7)) * ROWB
                                     + ((((lane >> 3) & 1) << 3)) * 2);

    float acc[4][4][4] = {};
    const int NT = K / 32;

    #pragma unroll
    for (int i = 0; i < 6; i++) cp16(ldSm[i], ldG[i]);
    cp_commit();

    for (int t = 0; t < NT; t++) {
        if (t + 1 < NT) {
            const uint32_t so = ((t + 1) & 1) * STAGEB;
            const int kc = (t + 1) * 32;
            #pragma unroll
            for (int i = 0; i < 6; i++) cp16(ldSm[i] + so, ldG[i] + kc);
            cp_commit();
            cp_wait1();
        } else {
            cp_wait0();
        }
        __syncthreads();

        const uint32_t st = smb + (t & 1) * STAGEB;
        #pragma unroll
        for (int ks = 0; ks < 32; ks += 16) {
            uint32_t ah[4][4], al[4][4], bh2[2][4];
            #pragma unroll
            for (int mi = 0; mi < 4; mi++) {
                ldsm4(ah[mi], st + aOff + mi * (16 * ROWB) + ks * 2);
                ldsm4(al[mi], st + BUFB + aOff + mi * (16 * ROWB) + ks * 2);
            }
            #pragma unroll
            for (int n2 = 0; n2 < 2; n2++)
                ldsm4(bh2[n2], st + 2 * BUFB + bOff + n2 * (16 * ROWB) + ks * 2);
            #pragma unroll
            for (int mi = 0; mi < 4; mi++)
                #pragma unroll
                for (int ni = 0; ni < 4; ni++) {
                    const uint32_t* bp = &bh2[ni >> 1][(ni & 1) * 2];
                    mma16816(acc[mi][ni], ah[mi], bp);
                    mma16816(acc[mi][ni], al[mi], bp);
                }
        }
        __syncthreads();
    }

    #pragma unroll
    for (int mi = 0; mi < 4; mi++)
        #pragma unroll
        for (int ni = 0; ni < 4; ni++) {
            #pragma unroll
            for (int half = 0; half < 2; half++) {
                const int r = bm + wm + mi * 16 + (lane >> 2) + half * 8;
                const int c = bn + wn + ni * 8 + (lane & 3) * 2;
                const size_t idx = (size_t)r * N + c;
                float d0 = acc[mi][ni][half * 2 + 0];
                float d1 = acc[mi][ni][half * 2 + 1];
                if (resid) {
                    const float2 q2 = *reinterpret_cast<const float2*>(&resid[idx]);
                    d0 += q2.x; d1 += q2.y;
                }
                if (Cf) *reinterpret_cast<float2*>(&Cf[idx]) = make_float2(d0, d1);
                if (Chi) {
                    __half2 h, l;
                    split_pair(d0, d1, &h, &l);
                    *reinterpret_cast<__half2*>(&Chi[idx]) = h;
                    if (Clo) *reinterpret_cast<__half2*>(&Clo[idx]) = l;
                }
            }
        }
}

// ------------------------- S = Q K^T, 128(q) x 64(k) tile --------------------
// 2 CTAs/SM: inputs 45KB (Qhi,Qlo,Khi) + mask 32KB = 77KB; S-stage reuses
// the input region after MMA.
#define ROWS_S 144                      // 64 fp16 (128B) + 16B pad
#define BUFQ (128 * ROWS_S)             // 18432
#define BUFK (64 * ROWS_S)              // 9216
#define MOFF2 (2 * BUFQ + BUFK)         // 46080
#define SROW 68
#define SA_SMEM (MOFF2 + 128 * 64 * 4)  // 78848

__global__ __launch_bounds__(256, 2)
void sgemm_attn(const fp16* __restrict__ Ahi, const fp16* __restrict__ Alo,
                const fp16* __restrict__ Bh,
                const int* __restrict__ mask, float* __restrict__ attn)
{
    extern __shared__ __align__(128) char sb[];
    const uint32_t smb = smem_u32(sb);
    float* Ssm = reinterpret_cast<float*>(sb);
    const int tid = threadIdx.x, lane = tid & 31, wid = tid >> 5;
    const int k0t = blockIdx.x * 64;
    const int q0 = blockIdx.y * 128;
    const int bh = blockIdx.z;
    const int b = bh >> 4, h = bh & 15;
    const size_t hoff = (size_t)h * DK;
    const int wm = (wid >> 1) * 32, wn = (wid & 1) * 32;

    // group A: inputs. Qhi/Qlo: 1024 chunks each; Khi: 512 chunks. 10/thread.
    #pragma unroll
    for (int i = 0; i < 4; i++) {
        const int chunk = tid + i * 256;
        const int r = chunk >> 3, j = chunk & 7;
        const size_t g = (size_t)(b * SS + q0 + r) * DM + hoff + j * 8;
        cp16(smb + r * ROWS_S + j * 16, Ahi + g);
        cp16(smb + BUFQ + r * ROWS_S + j * 16, Alo + g);
    }
    #pragma unroll
    for (int i = 0; i < 2; i++) {
        const int chunk = tid + i * 256;
        const int r = chunk >> 3, j = chunk & 7;
        cp16(smb + 2 * BUFQ + r * ROWS_S + j * 16,
             Bh + (size_t)(b * SS + k0t + r) * DM + hoff + j * 8);
    }
    cp_commit();

    // group B: mask tile 128x64 ints (2048 chunks of 16B, 8/thread)
    #pragma unroll
    for (int p = 0; p < 8; p++) {
        const int chunk = tid + p * 256;
        const int r = chunk >> 4, c4 = (chunk & 15) * 4;
        cp16(smb + MOFF2 + chunk * 16,
             &mask[((size_t)b * SS + q0 + r) * SS + k0t + c4]);
    }
    cp_commit();

    const uint32_t aOff = (uint32_t)((wm + (lane & 15)) * ROWS_S + (((lane >> 4) << 3)) * 2);
    const uint32_t bOff = (uint32_t)((wn + ((lane >> 4) << 3) + (lane & 7)) * ROWS_S
                                     + ((((lane >> 3) & 1) << 3)) * 2);

    cp_wait1();                      // inputs ready; mask still in flight
    __syncthreads();

    float acc[2][4][4] = {};
    #pragma unroll
    for (int ks = 0; ks < 64; ks += 16) {
        uint32_t ah[2][4], al[2][4], bh2[2][4];
        #pragma unroll
        for (int mi = 0; mi < 2; mi++) {
            ldsm4(ah[mi], smb + aOff + mi * (16 * ROWS_S) + ks * 2);
            ldsm4(al[mi], smb + BUFQ + aOff + mi * (16 * ROWS_S) + ks * 2);
        }
        #pragma unroll
        for (int n2 = 0; n2 < 2; n2++)
            ldsm4(bh2[n2], smb + 2 * BUFQ + bOff + n2 * (16 * ROWS_S) + ks * 2);
        #pragma unroll
        for (int mi = 0; mi < 2; mi++)
            #pragma unroll
            for (int ni = 0; ni < 4; ni++) {
                const uint32_t* bp = &bh2[ni >> 1][(ni & 1) * 2];
                mma16816(acc[mi][ni], ah[mi], bp);
                mma16816(acc[mi][ni], al[mi], bp);
            }
    }

    // stage S tile to smem (input region reused; mask region untouched)
    __syncthreads();
    #pragma unroll
    for (int mi = 0; mi < 2; mi++)
        #pragma unroll
        for (int ni = 0; ni < 4; ni++) {
            #pragma unroll
            for (int half = 0; half < 2; half++) {
                const int r = wm + mi * 16 + (lane >> 2) + half * 8;
                const int c = wn + ni * 8 + (lane & 3) * 2;
                *reinterpret_cast<float2*>(&Ssm[r * SROW + c]) =
                    make_float2(acc[mi][ni][half * 2 + 0],
                                acc[mi][ni][half * 2 + 1]);
            }
        }
    cp_wait0();                      // mask tile resident
    __syncthreads();

    // coalesced streaming writes; mask read from smem only
    int bad = 0;
    #pragma unroll
    for (int p = 0; p < 8; p++) {
        const int chunk = tid + p * 256;
        const int r = chunk >> 4, c4 = (chunk & 15) * 4;
        float4 v = *reinterpret_cast<const float4*>(&Ssm[r * SROW + c4]);
        const int4 m = *reinterpret_cast<const int4*>(sb + MOFF2 + chunk * 16);
        if (m.x == 0) { v.x = -1e9f; bad = 1; }
        if (m.y == 0) { v.y = -1e9f; bad = 1; }
        if (m.z == 0) { v.z = -1e9f; bad = 1; }
        if (m.w == 0) { v.w = -1e9f; bad = 1; }
        __stcs(reinterpret_cast<float4*>(
                   &attn[((size_t)bh * SS + q0 + r) * SS + k0t + c4]), v);
    }
    if (__syncthreads_or(bad)) {
        if (tid == 0) atomicExch(&g_flag, 0);
    }
}

// ------------------------- P = K^T V (64x64 per bh), split-K -----------------
__global__ __launch_bounds__(256)
void pk_kernel()
{
    if (g_flag == 0) return;
    __shared__ float Ks[32][68];
    __shared__ float Vs[32][68];
    const int bh = blockIdx.x, split = blockIdx.y;
    const int b = bh >> 4, h = bh & 15;
    const size_t hoff = (size_t)h * DK;
    const int tid = threadIdx.x;
    const int tx = tid & 15, ty = tid >> 4;
    const __half2* khh = reinterpret_cast<const __half2*>(g_kh_hi);
    const __half2* khl = reinterpret_cast<const __half2*>(g_kh_lo);
    const __half2* vhh = reinterpret_cast<const __half2*>(g_vh_hi);
    const __half2* vhl = reinterpret_cast<const __half2*>(g_vh_lo);
    float acc[4][4] = {};
    for (int it = 0; it < 8; it++) {
        const int s0 = split * 256 + it * 32;
        __syncthreads();
        #pragma unroll
        for (int t = 0; t < 2; t++) {
            const int idx = tid + t * 256;
            const int rr = idx >> 4, c4 = idx & 15;
            const size_t g2 = ((size_t)(b * SS + s0 + rr) * DM + hoff) / 2 + c4 * 2;
            float2 kh0 = __half22float2(khh[g2]),     kl0 = __half22float2(khl[g2]);
            float2 kh1 = __half22float2(khh[g2 + 1]), kl1 = __half22float2(khl[g2 + 1]);
            Ks[rr][c4 * 4 + 0] = kh0.x + kl0.x; Ks[rr][c4 * 4 + 1] = kh0.y + kl0.y;
            Ks[rr][c4 * 4 + 2] = kh1.x + kl1.x; Ks[rr][c4 * 4 + 3] = kh1.y + kl1.y;
            float2 vh0 = __half22float2(vhh[g2]),     vl0 = __half22float2(vhl[g2]);
            float2 vh1 = __half22float2(vhh[g2 + 1]), vl1 = __half22float2(vhl[g2 + 1]);
            Vs[rr][c4 * 4 + 0] = vh0.x + vl0.x; Vs[rr][c4 * 4 + 1] = vh0.y + vl0.y;
            Vs[rr][c4 * 4 + 2] = vh1.x + vl1.x; Vs[rr][c4 * 4 + 3] = vh1.y + vl1.y;
        }
        __syncthreads();
        #pragma unroll 4
        for (int s = 0; s < 32; s++) {
            const float4 vv = *reinterpret_cast<const float4*>(&Vs[s][tx * 4]);
            #pragma unroll
            for (int i = 0; i < 4; i++) {
                const float kv = Ks[s][ty * 4 + i];
                acc[i][0] += kv * vv.x; acc[i][1] += kv * vv.y;
                acc[i][2] += kv * vv.z; acc[i][3] += kv * vv.w;
            }
        }
    }
    #pragma unroll
    for (int i = 0; i < 4; i++)
        #pragma unroll
        for (int j = 0; j < 4; j++)
            atomicAdd(&g_P[bh * (DK * DK) + (ty * 4 + i) * DK + tx * 4 + j], acc[i][j]);
}

// ------------------------- O = Qs @ P (fast path) ----------------------------
__global__ __launch_bounds__(256)
void ofast_kernel()
{
    if (g_flag == 0) return;
    __shared__ float Qs[64][68];
    __shared__ float Ps[64][64];
    const int q0 = blockIdx.x * 64;
    const int bh = blockIdx.y;
    const int b = bh >> 4, h = bh & 15;
    const size_t hoff = (size_t)h * DK;
    const int tid = threadIdx.x;
    const int tx = tid & 15, ty = tid >> 4;
    const __half2* qhh = reinterpret_cast<const __half2*>(g_qh_hi);
    const __half2* qhl = reinterpret_cast<const __half2*>(g_qh_lo);
    #pragma unroll
    for (int t = 0; t < 4; t++) {
        const int idx = tid + t * 256;
        const int rr = idx >> 4, c4 = idx & 15;
        const size_t g2 = ((size_t)(b * SS + q0 + rr) * DM + hoff) / 2 + c4 * 2;
        float2 h0 = __half22float2(qhh[g2]),     l0 = __half22float2(qhl[g2]);
        float2 h1 = __half22float2(qhh[g2 + 1]), l1 = __half22float2(qhl[g2 + 1]);
        Qs[rr][c4 * 4 + 0] = h0.x + l0.x; Qs[rr][c4 * 4 + 1] = h0.y + l0.y;
        Qs[rr][c4 * 4 + 2] = h1.x + l1.x; Qs[rr][c4 * 4 + 3] = h1.y + l1.y;
        *reinterpret_cast<float4*>(&Ps[rr][c4 * 4]) =
            reinterpret_cast<const float4*>(g_P)[(size_t)bh * (DK * DK) / 4 + rr * 16 + c4];
    }
    __syncthreads();
    float acc[4][4] = {};
    #pragma unroll 8
    for (int d = 0; d < 64; d++) {
        const float4 pv = *reinterpret_cast<const float4*>(&Ps[d][tx * 4]);
        #pragma unroll
        for (int i = 0; i < 4; i++) {
            const float qv = Qs[ty * 4 + i][d];
            acc[i][0] += qv * pv.x; acc[i][1] += qv * pv.y;
            acc[i][2] += qv * pv.z; acc[i][3] += qv * pv.w;
        }
    }
    #pragma unroll
    for (int i = 0; i < 4; i++) {
        const size_t base = (size_t)(b * SS + q0 + ty * 4 + i) * DM + hoff + tx * 4;
        __half2 h0, l0, h1, l1;
        split_pair(acc[i][0], acc[i][1], &h0, &l0);
        split_pair(acc[i][2], acc[i][3], &h1, &l1);
        __half2* ph = reinterpret_cast<__half2*>(&g_oh_hi[base]);
        __half2* pl = reinterpret_cast<__half2*>(&g_oh_lo[base]);
        ph[0] = h0; ph[1] = h1;
        pl[0] = l0; pl[1] = l1;
    }
}

// ------------------------- O = attn @ V (fallback) ---------------------------
__global__ __launch_bounds__(256)
void ofb_kernel(const float* __restrict__ attn)
{
    if (g_flag != 0) return;
    __shared__ float As[64][68];
    __shared__ float Vs[64][68];
    const int q0 = blockIdx.x * 64;
    const int bh = blockIdx.y;
    const int b = bh >> 4, h = bh & 15;
    const size_t hoff = (size_t)h * DK;
    const int tid = threadIdx.x;
    const int tx = tid & 15, ty = tid >> 4;
    const __half2* vhh = reinterpret_cast<const __half2*>(g_vh_hi);
    const __half2* vhl = reinterpret_cast<const __half2*>(g_vh_lo);
    float acc[4][4] = {};
    for (int k0 = 0; k0 < SS; k0 += 64) {
        __syncthreads();
        #pragma unroll
        for (int t = 0; t < 4; t++) {
            const int idx = tid + t * 256;
            const int rr = idx >> 4, c4 = idx & 15;
            *reinterpret_cast<float4*>(&As[rr][c4 * 4]) =
                reinterpret_cast<const float4*>(attn)[(((size_t)bh * SS + q0 + rr) * SS + k0) / 4 + c4];
            const size_t g2 = ((size_t)(b * SS + k0 + rr) * DM + hoff) / 2 + c4 * 2;
            float2 h0 = __half22float2(vhh[g2]),     l0 = __half22float2(vhl[g2]);
            float2 h1 = __half22float2(vhh[g2 + 1]), l1 = __half22float2(vhl[g2 + 1]);
            Vs[rr][c4 * 4 + 0] = h0.x + l0.x; Vs[rr][c4 * 4 + 1] = h0.y + l0.y;
            Vs[rr][c4 * 4 + 2] = h1.x + l1.x; Vs[rr][c4 * 4 + 3] = h1.y + l1.y;
        }
        __syncthreads();
        #pragma unroll 8
        for (int kk = 0; kk < 64; kk++) {
            const float4 vv = *reinterpret_cast<const float4*>(&Vs[kk][tx * 4]);
            #pragma unroll
            for (int i = 0; i < 4; i++) {
                const float sv = As[ty * 4 + i][kk];
                acc[i][0] += sv * vv.x; acc[i][1] += sv * vv.y;
                acc[i][2] += sv * vv.z; acc[i][3] += sv * vv.w;
            }
        }
    }
    #pragma unroll
    for (int i = 0; i < 4; i++) {
        const size_t base = (size_t)(b * SS + q0 + ty * 4 + i) * DM + hoff + tx * 4;
        __half2 h0, l0, h1, l1;
        split_pair(acc[i][0], acc[i][1], &h0, &l0);
        split_pair(acc[i][2], acc[i][3], &h1, &l1);
        __half2* ph = reinterpret_cast<__half2*>(&g_oh_hi[base]);
        __half2* pl = reinterpret_cast<__half2*>(&g_oh_lo[base]);
        ph[0] = h0; ph[1] = h1;
        pl[0] = l0; pl[1] = l1;
    }
}

// ---------------------------------------------------------------------------
extern "C" void kernel_launch(void* const* d_in, const int* in_sizes, int n_in,
                              void* d_out, int out_size)
{
    const float* q     = (const float*)d_in[0];
    const float* k     = (const float*)d_in[1];
    const float* v     = (const float*)d_in[2];
    const int*   mask  = (const int*)  d_in[3];
    const float* Wq    = (const float*)d_in[4];
    const float* Wk    = (const float*)d_in[5];
    const float* Wv    = (const float*)d_in[6];
    const float* Wfc   = (const float*)d_in[7];
    const float* gamma = (const float*)d_in[8];
    const float* beta  = (const float*)d_in[9];
    float* out = (float*)d_out;
    float* attn = ((long long)out_size >= (long long)OUT_ELEMS + ATTN_ELEMS)
                      ? out + OUT_ELEMS : nullptr;

    void* p;
    #define SYM(T, name, sym) cudaGetSymbolAddress(&p, sym); T* name = (T*)p
    SYM(fp16, qn_hi, g_qn_hi); SYM(fp16, qn_lo, g_qn_lo);
    SYM(fp16, ki_hi, g_ki_hi); SYM(fp16, ki_lo, g_ki_lo);
    SYM(fp16, vi_hi, g_vi_hi); SYM(fp16, vi_lo, g_vi_lo);
    SYM(fp16, wq_hi, g_wq_hi);
    SYM(fp16, wk_hi, g_wk_hi);
    SYM(fp16, wv_hi, g_wv_hi);
    SYM(fp16, wf_hi, g_wf_hi);
    SYM(fp16, qh_hi, g_qh_hi); SYM(fp16, qh_lo, g_qh_lo);
    SYM(fp16, kh_hi, g_kh_hi); SYM(fp16, kh_lo, g_kh_lo);
    SYM(fp16, vh_hi, g_vh_hi); SYM(fp16, vh_lo, g_vh_lo);
    SYM(fp16, oh_hi, g_oh_hi); SYM(fp16, oh_lo, g_oh_lo);
    #undef SYM

    cudaFuncSetAttribute(tgemm, cudaFuncAttributeMaxDynamicSharedMemorySize, TG_SMEM);
    cudaFuncSetAttribute(sgemm_attn, cudaFuncAttributeMaxDynamicSharedMemorySize, SA_SMEM);

    // prep
    initk<<<512, 256>>>();
    if (!attn) maskchk<<<2048, 256>>>(mask);
    ln_kernel<<<NROWS, 256>>>(q, gamma, beta, qn_hi, qn_lo);
    splitk<<<NROWS * DM / 4 / 256, 256>>>(k, ki_hi, ki_lo, NROWS * DM / 4);
    splitk<<<NROWS * DM / 4 / 256, 256>>>(v, vi_hi, vi_lo, NROWS * DM / 4);
    dim3 wg(32, 32), wb(32, 8);
    wprep<<<wg, wb>>>(Wq, wq_hi);
    wprep<<<wg, wb>>>(Wk, wk_hi);
    wprep<<<wg, wb>>>(Wv, wv_hi);
    wprep<<<wg, wb>>>(Wfc, wf_hi);

    // projections (fp16 2-term mma.sync)
    dim3 gg(DM / 128, NROWS / 128);
    tgemm<<<gg, 256, TG_SMEM>>>(qn_hi, qn_lo, wq_hi,
                                nullptr, qh_hi, qh_lo, nullptr, DM, DM);
    tgemm<<<gg, 256, TG_SMEM>>>(ki_hi, ki_lo, wk_hi,
                                nullptr, kh_hi, kh_lo, nullptr, DM, DM);
    tgemm<<<gg, 256, TG_SMEM>>>(vi_hi, vi_lo, wv_hi,
                                nullptr, vh_hi, vh_lo, nullptr, DM, DM);

    // attn scores + smem-prefetched mask + all-ones flag (2 CTAs/SM)
    if (attn)
        sgemm_attn<<<dim3(SS / 64, SS / 128, BB * NH), 256, SA_SMEM>>>(
            qh_hi, qh_lo, kh_hi, mask, attn);

    // O: fast path (mask all-ones) or fallback
    pk_kernel<<<dim3(BB * NH, 8), 256>>>();
    ofast_kernel<<<dim3(SS / 64, BB * NH), 256>>>();
    if (attn)
        ofb_kernel<<<dim3(SS / 64, BB * NH), 256>>>(attn);

    // fc + residual
    tgemm<<<gg, 256, TG_SMEM>>>(oh_hi, oh_lo, wf_hi,
                                out, nullptr, nullptr, q, DM, DM);
}

// round 12
// speedup vs baseline: 1.3765x; 1.0777x over previous
#include <cuda_runtime.h>
#include <cuda_fp16.h>
#include <cstdint>

#define BB 2
#define SS 2048
#define DM 1024
#define NH 16
#define DK 64
#define NROWS (BB * SS)
#define OUT_ELEMS (NROWS * DM)
#define ATTN_ELEMS (2LL * 16 * 2048 * 2048)
#define INV_TEMP 0.35355339059327373f

typedef __half fp16;

// ------------------------- device scratch (no allocs) -----------------------
__device__ __align__(128) fp16  g_qn_hi[NROWS * DM], g_qn_lo[NROWS * DM];
__device__ __align__(128) fp16  g_ki_hi[NROWS * DM], g_ki_lo[NROWS * DM];
__device__ __align__(128) fp16  g_vi_hi[NROWS * DM], g_vi_lo[NROWS * DM];
__device__ __align__(128) fp16  g_wq_hi[DM * DM];
__device__ __align__(128) fp16  g_wk_hi[DM * DM];
__device__ __align__(128) fp16  g_wv_hi[DM * DM];
__device__ __align__(128) fp16  g_wf_hi[DM * DM];
__device__ __align__(128) fp16  g_qh_hi[NROWS * DM], g_qh_lo[NROWS * DM];
__device__ __align__(128) fp16  g_kh_hi[NROWS * DM], g_kh_lo[NROWS * DM];
__device__ __align__(128) fp16  g_vh_hi[NROWS * DM], g_vh_lo[NROWS * DM];
__device__ __align__(128) fp16  g_oh_hi[NROWS * DM], g_oh_lo[NROWS * DM];
__device__ __align__(128) float g_P[BB * NH * DK * DK];
__device__ int g_flag;

// ------------------------- helpers ------------------------------------------
__device__ __forceinline__ uint32_t smem_u32(const void* p) {
    uint32_t a;
    asm("{ .reg .u64 t; cvta.to.shared.u64 t, %1; cvt.u32.u64 %0, t; }"
        : "=r"(a) : "l"(p));
    return a;
}
__device__ __forceinline__ void cp16(uint32_t saddr, const void* g) {
    asm volatile("cp.async.cg.shared.global [%0], [%1], 16;"
                 :: "r"(saddr), "l"(g) : "memory");
}
__device__ __forceinline__ void cp_commit() {
    asm volatile("cp.async.commit_group;" ::: "memory");
}
__device__ __forceinline__ void cp_wait0() {
    asm volatile("cp.async.wait_group 0;" ::: "memory");
}
__device__ __forceinline__ void cp_wait1() {
    asm volatile("cp.async.wait_group 1;" ::: "memory");
}
__device__ __forceinline__ void ldsm4(uint32_t* r, uint32_t addr) {
    asm volatile("ldmatrix.sync.aligned.m8n8.x4.shared.b16 {%0,%1,%2,%3}, [%4];"
                 : "=r"(r[0]), "=r"(r[1]), "=r"(r[2]), "=r"(r[3]) : "r"(addr));
}
__device__ __forceinline__ void mma16816(float* d, const uint32_t* a,
                                         const uint32_t* b) {
    asm volatile(
        "mma.sync.aligned.m16n8k16.row.col.f32.f16.f16.f32 "
        "{%0,%1,%2,%3}, {%4,%5,%6,%7}, {%8,%9}, {%0,%1,%2,%3};"
        : "+f"(d[0]), "+f"(d[1]), "+f"(d[2]), "+f"(d[3])
        : "r"(a[0]), "r"(a[1]), "r"(a[2]), "r"(a[3]), "r"(b[0]), "r"(b[1]));
}
__device__ __forceinline__ void split_pair(float x, float y, __half2* hi,
                                           __half2* lo) {
    __half2 h = __floats2half2_rn(x, y);
    *hi = h;
    *lo = __floats2half2_rn(x - __half2float(__low2half(h)),
                            y - __half2float(__high2half(h)));
}

// ------------------------- small prep kernels --------------------------------
__global__ void initk() {
    int i = blockIdx.x * 256 + threadIdx.x;
    if (i < BB * NH * DK * DK) g_P[i] = 0.0f;
    if (i == 0) g_flag = 1;
}

// fallback full-mask check (only used when attn buffer absent)
__global__ void maskchk(const int* __restrict__ mask) {
    const int4* m4 = reinterpret_cast<const int4*>(mask);
    const size_t total = (size_t)BB * SS * SS / 4;
    size_t i = (size_t)blockIdx.x * 256 + threadIdx.x;
    size_t stride = (size_t)gridDim.x * 256;
    int bad = 0;
    for (size_t j = i; j < total; j += stride) {
        int4 m = __ldcs(&m4[j]);
        if (!(m.x && m.y && m.z && m.w)) bad = 1;
    }
    if (bad) g_flag = 0;
}

__global__ void ln_kernel(const float* __restrict__ q,
                          const float* __restrict__ gamma,
                          const float* __restrict__ beta,
                          fp16* __restrict__ out_hi, fp16* __restrict__ out_lo) {
    __shared__ float red[16];
    const int row = blockIdx.x;
    const int tid = threadIdx.x;
    const float4 v = reinterpret_cast<const float4*>(q)[row * 256 + tid];
    float s  = v.x + v.y + v.z + v.w;
    float s2 = v.x * v.x + v.y * v.y + v.z * v.z + v.w * v.w;
    #pragma unroll
    for (int o = 16; o > 0; o >>= 1) {
        s  += __shfl_xor_sync(0xffffffffu, s,  o);
        s2 += __shfl_xor_sync(0xffffffffu, s2, o);
    }
    if ((tid & 31) == 0) { red[tid >> 5] = s; red[8 + (tid >> 5)] = s2; }
    __syncthreads();
    if (tid < 32) {
        s  = (tid < 8) ? red[tid]     : 0.0f;
        s2 = (tid < 8) ? red[8 + tid] : 0.0f;
        #pragma unroll
        for (int o = 4; o > 0; o >>= 1) {
            s  += __shfl_xor_sync(0xffffffffu, s,  o);
            s2 += __shfl_xor_sync(0xffffffffu, s2, o);
        }
        if (tid == 0) { red[0] = s; red[8] = s2; }
    }
    __syncthreads();
    const float mu   = red[0] * (1.0f / 1024.0f);
    const float var  = red[8] * (1.0f / 1024.0f) - mu * mu;
    const float rstd = rsqrtf(var + 1e-6f);
    const float4 g  = reinterpret_cast<const float4*>(gamma)[tid];
    const float4 bb = reinterpret_cast<const float4*>(beta)[tid];
    float y0 = ((v.x - mu) * rstd * g.x + bb.x) * INV_TEMP;
    float y1 = ((v.y - mu) * rstd * g.y + bb.y) * INV_TEMP;
    float y2 = ((v.z - mu) * rstd * g.z + bb.z) * INV_TEMP;
    float y3 = ((v.w - mu) * rstd * g.w + bb.w) * INV_TEMP;
    __half2 h0, l0, h1, l1;
    split_pair(y0, y1, &h0, &l0);
    split_pair(y2, y3, &h1, &l1);
    __half2* oh = reinterpret_cast<__half2*>(out_hi);
    __half2* ol = reinterpret_cast<__half2*>(out_lo);
    const int b2 = (row * 256 + tid) * 2;
    oh[b2] = h0; oh[b2 + 1] = h1;
    ol[b2] = l0; ol[b2 + 1] = l1;
}

__global__ void splitk(const float* __restrict__ x, fp16* __restrict__ hi,
                       fp16* __restrict__ lo, int n4) {
    int i = blockIdx.x * 256 + threadIdx.x;
    if (i >= n4) return;
    float4 v = reinterpret_cast<const float4*>(x)[i];
    __half2 h0, l0, h1, l1;
    split_pair(v.x, v.y, &h0, &l0);
    split_pair(v.z, v.w, &h1, &l1);
    reinterpret_cast<__half2*>(hi)[i * 2]     = h0;
    reinterpret_cast<__half2*>(hi)[i * 2 + 1] = h1;
    reinterpret_cast<__half2*>(lo)[i * 2]     = l0;
    reinterpret_cast<__half2*>(lo)[i * 2 + 1] = l1;
}

// W[K][N] -> WT[n][k] hi fp16 (transpose)
__global__ void wprep(const float* __restrict__ W, fp16* __restrict__ Thi) {
    __shared__ float t[32][33];
    const int n0 = blockIdx.x * 32, k0 = blockIdx.y * 32;
    const int tx = threadIdx.x, ty = threadIdx.y;
    #pragma unroll
    for (int r = 0; r < 4; r++)
        t[ty + r * 8][tx] = W[(size_t)(k0 + ty + r * 8) * DM + n0 + tx];
    __syncthreads();
    #pragma unroll
    for (int r = 0; r < 4; r++) {
        const int nl = ty + r * 8;
        Thi[(size_t)(n0 + nl) * DM + k0 + tx] = __float2half_rn(t[tx][nl]);
    }
}

// ------------------------- mma.sync GEMM (fp16 2-term) -----------------------
#define ROWB 80
#define BUFB (128 * ROWB)
#define STAGEB (3 * BUFB)
#define TG_SMEM (2 * STAGEB)

__global__ __launch_bounds__(256, 1)
void tgemm(const fp16* __restrict__ Ahi, const fp16* __restrict__ Alo,
           const fp16* __restrict__ Bh, float* __restrict__ Cf,
           fp16* __restrict__ Chi, fp16* __restrict__ Clo,
           const float* __restrict__ resid, int N, int K)
{
    extern __shared__ __align__(128) char sb[];
    const uint32_t smb = smem_u32(sb);
    const int tid = threadIdx.x, lane = tid & 31, wid = tid >> 5;
    const int bm = blockIdx.y * 128, bn = blockIdx.x * 128;
    const int wm = (wid >> 2) * 64, wn = (wid & 3) * 32;

    uint32_t ldSm[6]; const fp16* ldG[6];
    #pragma unroll
    for (int i = 0; i < 6; i++) {
        const int buf = i >> 1;
        const int chunk = tid + (i & 1) * 256;
        const int r = chunk >> 2, j = chunk & 3;
        ldSm[i] = smb + buf * BUFB + r * ROWB + j * 16;
        const fp16* base = (buf == 0) ? Ahi : (buf == 1) ? Alo : Bh;
        const int rowg = (buf < 2) ? (bm + r) : (bn + r);
        ldG[i] = base + (size_t)rowg * K + j * 8;
    }

    const uint32_t aOff = (uint32_t)((wm + (lane & 15)) * ROWB + (((lane >> 4) << 3)) * 2);
    const uint32_t bOff = (uint32_t)((wn + ((lane >> 4) << 3) + (lane & 7)) * ROWB
                                     + ((((lane >> 3) & 1) << 3)) * 2);

    float acc[4][4][4] = {};
    const int NT = K / 32;

    #pragma unroll
    for (int i = 0; i < 6; i++) cp16(ldSm[i], ldG[i]);
    cp_commit();

    for (int t = 0; t < NT; t++) {
        if (t + 1 < NT) {
            const uint32_t so = ((t + 1) & 1) * STAGEB;
            const int kc = (t + 1) * 32;
            #pragma unroll
            for (int i = 0; i < 6; i++) cp16(ldSm[i] + so, ldG[i] + kc);
            cp_commit();
            cp_wait1();
        } else {
            cp_wait0();
        }
        __syncthreads();

        const uint32_t st = smb + (t & 1) * STAGEB;
        #pragma unroll
        for (int ks = 0; ks < 32; ks += 16) {
            uint32_t ah[4][4], al[4][4], bh2[2][4];
            #pragma unroll
            for (int mi = 0; mi < 4; mi++) {
                ldsm4(ah[mi], st + aOff + mi * (16 * ROWB) + ks * 2);
                ldsm4(al[mi], st + BUFB + aOff + mi * (16 * ROWB) + ks * 2);
            }
            #pragma unroll
            for (int n2 = 0; n2 < 2; n2++)
                ldsm4(bh2[n2], st + 2 * BUFB + bOff + n2 * (16 * ROWB) + ks * 2);
            #pragma unroll
            for (int mi = 0; mi < 4; mi++)
                #pragma unroll
                for (int ni = 0; ni < 4; ni++) {
                    const uint32_t* bp = &bh2[ni >> 1][(ni & 1) * 2];
                    mma16816(acc[mi][ni], ah[mi], bp);
                    mma16816(acc[mi][ni], al[mi], bp);
                }
        }
        __syncthreads();
    }

    #pragma unroll
    for (int mi = 0; mi < 4; mi++)
        #pragma unroll
        for (int ni = 0; ni < 4; ni++) {
            #pragma unroll
            for (int half = 0; half < 2; half++) {
                const int r = bm + wm + mi * 16 + (lane >> 2) + half * 8;
                const int c = bn + wn + ni * 8 + (lane & 3) * 2;
                const size_t idx = (size_t)r * N + c;
                float d0 = acc[mi][ni][half * 2 + 0];
                float d1 = acc[mi][ni][half * 2 + 1];
                if (resid) {
                    const float2 q2 = *reinterpret_cast<const float2*>(&resid[idx]);
                    d0 += q2.x; d1 += q2.y;
                }
                if (Cf) *reinterpret_cast<float2*>(&Cf[idx]) = make_float2(d0, d1);
                if (Chi) {
                    __half2 h, l;
                    split_pair(d0, d1, &h, &l);
                    *reinterpret_cast<__half2*>(&Chi[idx]) = h;
                    if (Clo) *reinterpret_cast<__half2*>(&Clo[idx]) = l;
                }
            }
        }
}

// ------------------------- S = Qhi Khi^T, 128(q) x 64(k) tile ----------------
// Single-term MMA. Grid (h, ktile, b*16+qtile) so the 16 heads sharing a mask
// tile are adjacent in issue order -> mask served from L2.
#define ROWS_S 144                      // 64 fp16 (128B) + 16B pad
#define BUFQ1 (128 * ROWS_S)            // 18432 (Qhi)
#define KOFF  BUFQ1                     // Khi at 18432 (9216 bytes)
#define SSTAGE (BUFQ1 + 64 * ROWS_S)    // 27648
#define SROW 68
#define MOFF3 (SSTAGE + 128 * SROW * 4) // 62464
#define SA_SMEM (MOFF3 + 128 * 64 * 4)  // 95232

__global__ __launch_bounds__(256, 2)
void sgemm_attn(const fp16* __restrict__ Ahi, const fp16* __restrict__ Bh,
                const int* __restrict__ mask, float* __restrict__ attn)
{
    extern __shared__ __align__(128) char sb[];
    const uint32_t smb = smem_u32(sb);
    float* Ssm = reinterpret_cast<float*>(sb + SSTAGE);
    const int tid = threadIdx.x, lane = tid & 31, wid = tid >> 5;
    const int h = blockIdx.x;
    const int k0t = blockIdx.y * 64;
    const int zz = blockIdx.z;
    const int b = zz >> 4;
    const int q0 = (zz & 15) * 128;
    const int bh = b * NH + h;
    const size_t hoff = (size_t)h * DK;
    const int wm = (wid >> 1) * 32, wn = (wid & 1) * 32;

    // group A: Qhi (1024 chunks, 4/thread) + Khi (512 chunks, 2/thread)
    #pragma unroll
    for (int i = 0; i < 4; i++) {
        const int chunk = tid + i * 256;
        const int r = chunk >> 3, j = chunk & 7;
        cp16(smb + r * ROWS_S + j * 16,
             Ahi + (size_t)(b * SS + q0 + r) * DM + hoff + j * 8);
    }
    #pragma unroll
    for (int i = 0; i < 2; i++) {
        const int chunk = tid + i * 256;
        const int r = chunk >> 3, j = chunk & 7;
        cp16(smb + KOFF + r * ROWS_S + j * 16,
             Bh + (size_t)(b * SS + k0t + r) * DM + hoff + j * 8);
    }
    cp_commit();

    // group B: mask tile 128x64 ints (2048 chunks, 8/thread)
    #pragma unroll
    for (int p = 0; p < 8; p++) {
        const int chunk = tid + p * 256;
        const int r = chunk >> 4, c4 = (chunk & 15) * 4;
        cp16(smb + MOFF3 + chunk * 16,
             &mask[((size_t)b * SS + q0 + r) * SS + k0t + c4]);
    }
    cp_commit();

    const uint32_t aOff = (uint32_t)((wm + (lane & 15)) * ROWS_S + (((lane >> 4) << 3)) * 2);
    const uint32_t bOff = (uint32_t)(KOFF + (wn + ((lane >> 4) << 3) + (lane & 7)) * ROWS_S
                                     + ((((lane >> 3) & 1) << 3)) * 2);

    cp_wait1();                      // inputs ready; mask still in flight
    __syncthreads();

    float acc[2][4][4] = {};
    #pragma unroll
    for (int ks = 0; ks < 64; ks += 16) {
        uint32_t ah[2][4], bh2[2][4];
        #pragma unroll
        for (int mi = 0; mi < 2; mi++)
            ldsm4(ah[mi], smb + aOff + mi * (16 * ROWS_S) + ks * 2);
        #pragma unroll
        for (int n2 = 0; n2 < 2; n2++)
            ldsm4(bh2[n2], smb + bOff + n2 * (16 * ROWS_S) + ks * 2);
        #pragma unroll
        for (int mi = 0; mi < 2; mi++)
            #pragma unroll
            for (int ni = 0; ni < 4; ni++)
                mma16816(acc[mi][ni], ah[mi], &bh2[ni >> 1][(ni & 1) * 2]);
    }

    // stage S tile to smem (separate region; no dependency on inputs)
    #pragma unroll
    for (int mi = 0; mi < 2; mi++)
        #pragma unroll
        for (int ni = 0; ni < 4; ni++) {
            #pragma unroll
            for (int half = 0; half < 2; half++) {
                const int r = wm + mi * 16 + (lane >> 2) + half * 8;
                const int c = wn + ni * 8 + (lane & 3) * 2;
                *reinterpret_cast<float2*>(&Ssm[r * SROW + c]) =
                    make_float2(acc[mi][ni][half * 2 + 0],
                                acc[mi][ni][half * 2 + 1]);
            }
        }
    cp_wait0();                      // mask tile resident
    __syncthreads();

    // coalesced streaming writes; mask read from smem only
    int bad = 0;
    #pragma unroll
    for (int p = 0; p < 8; p++) {
        const int chunk = tid + p * 256;
        const int r = chunk >> 4, c4 = (chunk & 15) * 4;
        float4 v = *reinterpret_cast<const float4*>(&Ssm[r * SROW + c4]);
        const int4 m = *reinterpret_cast<const int4*>(sb + MOFF3 + chunk * 16);
        if (m.x == 0) { v.x = -1e9f; bad = 1; }
        if (m.y == 0) { v.y = -1e9f; bad = 1; }
        if (m.z == 0) { v.z = -1e9f; bad = 1; }
        if (m.w == 0) { v.w = -1e9f; bad = 1; }
        __stcs(reinterpret_cast<float4*>(
                   &attn[((size_t)bh * SS + q0 + r) * SS + k0t + c4]), v);
    }
    if (__syncthreads_or(bad)) {
        if (tid == 0) atomicExch(&g_flag, 0);
    }
}

// ------------------------- P = K^T V (64x64 per bh), split-K -----------------
__global__ __launch_bounds__(256)
void pk_kernel()
{
    if (g_flag == 0) return;
    __shared__ float Ks[32][68];
    __shared__ float Vs[32][68];
    const int bh = blockIdx.x, split = blockIdx.y;
    const int b = bh >> 4, h = bh & 15;
    const size_t hoff = (size_t)h * DK;
    const int tid = threadIdx.x;
    const int tx = tid & 15, ty = tid >> 4;
    const __half2* khh = reinterpret_cast<const __half2*>(g_kh_hi);
    const __half2* khl = reinterpret_cast<const __half2*>(g_kh_lo);
    const __half2* vhh = reinterpret_cast<const __half2*>(g_vh_hi);
    const __half2* vhl = reinterpret_cast<const __half2*>(g_vh_lo);
    float acc[4][4] = {};
    for (int it = 0; it < 8; it++) {
        const int s0 = split * 256 + it * 32;
        __syncthreads();
        #pragma unroll
        for (int t = 0; t < 2; t++) {
            const int idx = tid + t * 256;
            const int rr = idx >> 4, c4 = idx & 15;
            const size_t g2 = ((size_t)(b * SS + s0 + rr) * DM + hoff) / 2 + c4 * 2;
            float2 kh0 = __half22float2(khh[g2]),     kl0 = __half22float2(khl[g2]);
            float2 kh1 = __half22float2(khh[g2 + 1]), kl1 = __half22float2(khl[g2 + 1]);
            Ks[rr][c4 * 4 + 0] = kh0.x + kl0.x; Ks[rr][c4 * 4 + 1] = kh0.y + kl0.y;
            Ks[rr][c4 * 4 + 2] = kh1.x + kl1.x; Ks[rr][c4 * 4 + 3] = kh1.y + kl1.y;
            float2 vh0 = __half22float2(vhh[g2]),     vl0 = __half22float2(vhl[g2]);
            float2 vh1 = __half22float2(vhh[g2 + 1]), vl1 = __half22float2(vhl[g2 + 1]);
            Vs[rr][c4 * 4 + 0] = vh0.x + vl0.x; Vs[rr][c4 * 4 + 1] = vh0.y + vl0.y;
            Vs[rr][c4 * 4 + 2] = vh1.x + vl1.x; Vs[rr][c4 * 4 + 3] = vh1.y + vl1.y;
        }
        __syncthreads();
        #pragma unroll 4
        for (int s = 0; s < 32; s++) {
            const float4 vv = *reinterpret_cast<const float4*>(&Vs[s][tx * 4]);
            #pragma unroll
            for (int i = 0; i < 4; i++) {
                const float kv = Ks[s][ty * 4 + i];
                acc[i][0] += kv * vv.x; acc[i][1] += kv * vv.y;
                acc[i][2] += kv * vv.z; acc[i][3] += kv * vv.w;
            }
        }
    }
    #pragma unroll
    for (int i = 0; i < 4; i++)
        #pragma unroll
        for (int j = 0; j < 4; j++)
            atomicAdd(&g_P[bh * (DK * DK) + (ty * 4 + i) * DK + tx * 4 + j], acc[i][j]);
}

// ------------------------- O = Qs @ P (fast path) ----------------------------
__global__ __launch_bounds__(256)
void ofast_kernel()
{
    if (g_flag == 0) return;
    __shared__ float Qs[64][68];
    __shared__ float Ps[64][64];
    const int q0 = blockIdx.x * 64;
    const int bh = blockIdx.y;
    const int b = bh >> 4, h = bh & 15;
    const size_t hoff = (size_t)h * DK;
    const int tid = threadIdx.x;
    const int tx = tid & 15, ty = tid >> 4;
    const __half2* qhh = reinterpret_cast<const __half2*>(g_qh_hi);
    const __half2* qhl = reinterpret_cast<const __half2*>(g_qh_lo);
    #pragma unroll
    for (int t = 0; t < 4; t++) {
        const int idx = tid + t * 256;
        const int rr = idx >> 4, c4 = idx & 15;
        const size_t g2 = ((size_t)(b * SS + q0 + rr) * DM + hoff) / 2 + c4 * 2;
        float2 h0 = __half22float2(qhh[g2]),     l0 = __half22float2(qhl[g2]);
        float2 h1 = __half22float2(qhh[g2 + 1]), l1 = __half22float2(qhl[g2 + 1]);
        Qs[rr][c4 * 4 + 0] = h0.x + l0.x; Qs[rr][c4 * 4 + 1] = h0.y + l0.y;
        Qs[rr][c4 * 4 + 2] = h1.x + l1.x; Qs[rr][c4 * 4 + 3] = h1.y + l1.y;
        *reinterpret_cast<float4*>(&Ps[rr][c4 * 4]) =
            reinterpret_cast<const float4*>(g_P)[(size_t)bh * (DK * DK) / 4 + rr * 16 + c4];
    }
    __syncthreads();
    float acc[4][4] = {};
    #pragma unroll 8
    for (int d = 0; d < 64; d++) {
        const float4 pv = *reinterpret_cast<const float4*>(&Ps[d][tx * 4]);
        #pragma unroll
        for (int i = 0; i < 4; i++) {
            const float qv = Qs[ty * 4 + i][d];
            acc[i][0] += qv * pv.x; acc[i][1] += qv * pv.y;
            acc[i][2] += qv * pv.z; acc[i][3] += qv * pv.w;
        }
    }
    #pragma unroll
    for (int i = 0; i < 4; i++) {
        const size_t base = (size_t)(b * SS + q0 + ty * 4 + i) * DM + hoff + tx * 4;
        __half2 h0, l0, h1, l1;
        split_pair(acc[i][0], acc[i][1], &h0, &l0);
        split_pair(acc[i][2], acc[i][3], &h1, &l1);
        __half2* ph = reinterpret_cast<__half2*>(&g_oh_hi[base]);
        __half2* pl = reinterpret_cast<__half2*>(&g_oh_lo[base]);
        ph[0] = h0; ph[1] = h1;
        pl[0] = l0; pl[1] = l1;
    }
}

// ------------------------- O = attn @ V (fallback) ---------------------------
__global__ __launch_bounds__(256)
void ofb_kernel(const float* __restrict__ attn)
{
    if (g_flag != 0) return;
    __shared__ float As[64][68];
    __shared__ float Vs[64][68];
    const int q0 = blockIdx.x * 64;
    const int bh = blockIdx.y;
    const int b = bh >> 4, h = bh & 15;
    const size_t hoff = (size_t)h * DK;
    const int tid = threadIdx.x;
    const int tx = tid & 15, ty = tid >> 4;
    const __half2* vhh = reinterpret_cast<const __half2*>(g_vh_hi);
    const __half2* vhl = reinterpret_cast<const __half2*>(g_vh_lo);
    float acc[4][4] = {};
    for (int k0 = 0; k0 < SS; k0 += 64) {
        __syncthreads();
        #pragma unroll
        for (int t = 0; t < 4; t++) {
            const int idx = tid + t * 256;
            const int rr = idx >> 4, c4 = idx & 15;
            *reinterpret_cast<float4*>(&As[rr][c4 * 4]) =
                reinterpret_cast<const float4*>(attn)[(((size_t)bh * SS + q0 + rr) * SS + k0) / 4 + c4];
            const size_t g2 = ((size_t)(b * SS + k0 + rr) * DM + hoff) / 2 + c4 * 2;
            float2 h0 = __half22float2(vhh[g2]),     l0 = __half22float2(vhl[g2]);
            float2 h1 = __half22float2(vhh[g2 + 1]), l1 = __half22float2(vhl[g2 + 1]);
            Vs[rr][c4 * 4 + 0] = h0.x + l0.x; Vs[rr][c4 * 4 + 1] = h0.y + l0.y;
            Vs[rr][c4 * 4 + 2] = h1.x + l1.x; Vs[rr][c4 * 4 + 3] = h1.y + l1.y;
        }
        __syncthreads();
        #pragma unroll 8
        for (int kk = 0; kk < 64; kk++) {
            const float4 vv = *reinterpret_cast<const float4*>(&Vs[kk][tx * 4]);
            #pragma unroll
            for (int i = 0; i < 4; i++) {
                const float sv = As[ty * 4 + i][kk];
                acc[i][0] += sv * vv.x; acc[i][1] += sv * vv.y;
                acc[i][2] += sv * vv.z; acc[i][3] += sv * vv.w;
            }
        }
    }
    #pragma unroll
    for (int i = 0; i < 4; i++) {
        const size_t base = (size_t)(b * SS + q0 + ty * 4 + i) * DM + hoff + tx * 4;
        __half2 h0, l0, h1, l1;
        split_pair(acc[i][0], acc[i][1], &h0, &l0);
        split_pair(acc[i][2], acc[i][3], &h1, &l1);
        __half2* ph = reinterpret_cast<__half2*>(&g_oh_hi[base]);
        __half2* pl = reinterpret_cast<__half2*>(&g_oh_lo[base]);
        ph[0] = h0; ph[1] = h1;
        pl[0] = l0; pl[1] = l1;
    }
}

// ---------------------------------------------------------------------------
extern "C" void kernel_launch(void* const* d_in, const int* in_sizes, int n_in,
                              void* d_out, int out_size)
{
    const float* q     = (const float*)d_in[0];
    const float* k     = (const float*)d_in[1];
    const float* v     = (const float*)d_in[2];
    const int*   mask  = (const int*)  d_in[3];
    const float* Wq    = (const float*)d_in[4];
    const float* Wk    = (const float*)d_in[5];
    const float* Wv    = (const float*)d_in[6];
    const float* Wfc   = (const float*)d_in[7];
    const float* gamma = (const float*)d_in[8];
    const float* beta  = (const float*)d_in[9];
    float* out = (float*)d_out;
    float* attn = ((long long)out_size >= (long long)OUT_ELEMS + ATTN_ELEMS)
                      ? out + OUT_ELEMS : nullptr;

    void* p;
    #define SYM(T, name, sym) cudaGetSymbolAddress(&p, sym); T* name = (T*)p
    SYM(fp16, qn_hi, g_qn_hi); SYM(fp16, qn_lo, g_qn_lo);
    SYM(fp16, ki_hi, g_ki_hi); SYM(fp16, ki_lo, g_ki_lo);
    SYM(fp16, vi_hi, g_vi_hi); SYM(fp16, vi_lo, g_vi_lo);
    SYM(fp16, wq_hi, g_wq_hi);
    SYM(fp16, wk_hi, g_wk_hi);
    SYM(fp16, wv_hi, g_wv_hi);
    SYM(fp16, wf_hi, g_wf_hi);
    SYM(fp16, qh_hi, g_qh_hi); SYM(fp16, qh_lo, g_qh_lo);
    SYM(fp16, kh_hi, g_kh_hi); SYM(fp16, kh_lo, g_kh_lo);
    SYM(fp16, vh_hi, g_vh_hi); SYM(fp16, vh_lo, g_vh_lo);
    SYM(fp16, oh_hi, g_oh_hi); SYM(fp16, oh_lo, g_oh_lo);
    #undef SYM

    cudaFuncSetAttribute(tgemm, cudaFuncAttributeMaxDynamicSharedMemorySize, TG_SMEM);
    cudaFuncSetAttribute(sgemm_attn, cudaFuncAttributeMaxDynamicSharedMemorySize, SA_SMEM);

    // prep
    initk<<<512, 256>>>();
    if (!attn) maskchk<<<2048, 256>>>(mask);
    ln_kernel<<<NROWS, 256>>>(q, gamma, beta, qn_hi, qn_lo);
    splitk<<<NROWS * DM / 4 / 256, 256>>>(k, ki_hi, ki_lo, NROWS * DM / 4);
    splitk<<<NROWS * DM / 4 / 256, 256>>>(v, vi_hi, vi_lo, NROWS * DM / 4);
    dim3 wg(32, 32), wb(32, 8);
    wprep<<<wg, wb>>>(Wq, wq_hi);
    wprep<<<wg, wb>>>(Wk, wk_hi);
    wprep<<<wg, wb>>>(Wv, wv_hi);
    wprep<<<wg, wb>>>(Wfc, wf_hi);

    // projections (fp16 2-term mma.sync)
    dim3 gg(DM / 128, NROWS / 128);
    tgemm<<<gg, 256, TG_SMEM>>>(qn_hi, qn_lo, wq_hi,
                                nullptr, qh_hi, qh_lo, nullptr, DM, DM);
    tgemm<<<gg, 256, TG_SMEM>>>(ki_hi, ki_lo, wk_hi,
                                nullptr, kh_hi, kh_lo, nullptr, DM, DM);
    tgemm<<<gg, 256, TG_SMEM>>>(vi_hi, vi_lo, wv_hi,
                                nullptr, vh_hi, vh_lo, nullptr, DM, DM);

    // attn scores: single-term MMA, head-major grid for mask L2 reuse
    if (attn)
        sgemm_attn<<<dim3(NH, SS / 64, BB * (SS / 128)), 256, SA_SMEM>>>(
            qh_hi, kh_hi, mask, attn);

    // O: fast path (mask all-ones) or fallback
    pk_kernel<<<dim3(BB * NH, 8), 256>>>();
    ofast_kernel<<<dim3(SS / 64, BB * NH), 256>>>();
    if (attn)
        ofb_kernel<<<dim3(SS / 64, BB * NH), 256>>>(attn);

    // fc + residual
    tgemm<<<gg, 256, TG_SMEM>>>(oh_hi, oh_lo, wf_hi,
                                out, nullptr, nullptr, q, DM, DM);
}